// round 13
// baseline (speedup 1.0000x reference)
#include <cuda_runtime.h>
#include <cuda_fp16.h>
#include <math.h>
#include <stdint.h>

#define BB 8
#define NTOK 2048
#define CLIPD 512
#define DD 256
#define BDIM 128
#define NCLS 10
#define ROWS (BB * NTOK)   // 16384
#define QKVN 768

// ---------------- scratch (no cudaMalloc allowed) ----------------
__device__ __half g_lf  [ROWS * CLIPD];
__device__ __half g_h16 [ROWS * DD];
__device__ __half g_qkv [ROWS * QKVN];         // q | k | v fp16, row stride 768
__device__ __half g_ent [DD * CLIPD];
__device__ __half g_wqkvt[QKVN * DD];
__device__ float  g_bqkv[QKVN];
__device__ __half g_bnt [BDIM * DD];           // bn_w^T [128][256]
__device__ float  g_pp  [BB * 16 * BDIM];      // pool partials per (b, q-tile)

// ---------------- mma / ldmatrix / cp.async helpers ----------------
__device__ __forceinline__ uint32_t smem_u32(const void* p) {
    uint32_t a;
    asm("{ .reg .u64 t; cvta.to.shared.u64 t, %1; cvt.u32.u64 %0, t; }" : "=r"(a) : "l"(p));
    return a;
}
__device__ __forceinline__ void ldsm4(uint32_t* r, uint32_t addr) {
    asm volatile("ldmatrix.sync.aligned.m8n8.x4.shared.b16 {%0,%1,%2,%3}, [%4];"
                 : "=r"(r[0]), "=r"(r[1]), "=r"(r[2]), "=r"(r[3]) : "r"(addr));
}
__device__ __forceinline__ void ldsm4t(uint32_t* r, uint32_t addr) {
    asm volatile("ldmatrix.sync.aligned.m8n8.x4.trans.shared.b16 {%0,%1,%2,%3}, [%4];"
                 : "=r"(r[0]), "=r"(r[1]), "=r"(r[2]), "=r"(r[3]) : "r"(addr));
}
__device__ __forceinline__ void mma_f16(float* d, const uint32_t* a, const uint32_t* b) {
    asm volatile(
        "mma.sync.aligned.m16n8k16.row.col.f32.f16.f16.f32 "
        "{%0,%1,%2,%3}, {%4,%5,%6,%7}, {%8,%9}, {%0,%1,%2,%3};"
        : "+f"(d[0]), "+f"(d[1]), "+f"(d[2]), "+f"(d[3])
        : "r"(a[0]), "r"(a[1]), "r"(a[2]), "r"(a[3]), "r"(b[0]), "r"(b[1]));
}
__device__ __forceinline__ void cp16(uint32_t dst, const void* src) {
    asm volatile("cp.async.cg.shared.global [%0], [%1], 16;" :: "r"(dst), "l"(src));
}
#define CP_COMMIT() asm volatile("cp.async.commit_group;" ::: "memory")
#define CP_WAIT1()  asm volatile("cp.async.wait_group 1;" ::: "memory")
#define CP_WAIT0()  asm volatile("cp.async.wait_group 0;" ::: "memory")

// ---------------- fp16 HMMA GEMM, 3-stage cp.async pipeline (128x128 tile) ----------------
#define LDSR 40
#define STAGE_B (128 * LDSR * 2)
#define GEMM_SMEM (6 * STAGE_B)

__global__ void __launch_bounds__(256) gemm_mma(
    const __half* __restrict__ A, const __half* __restrict__ B,
    __half* __restrict__ Ch,
    int N, int K, const float* __restrict__ bias)
{
    extern __shared__ char smem[];
    const int tid = threadIdx.x;
    const int wid = tid >> 5, lid = tid & 31;
    const int wm = wid & 3, wn = wid >> 2;
    const int row0 = blockIdx.y * 128;
    const int col0 = blockIdx.x * 128;
    const int T = K / 32;

    const int lr = tid >> 1;
    const int lk = (tid & 1) * 16;

    const uint32_t sBase = smem_u32(smem);
    const uint32_t aS = sBase;
    const uint32_t bS = sBase + 3 * STAGE_B;
    const uint32_t dstOff = (uint32_t)(lr * LDSR + lk) * 2;

    const __half* ag = A + (long)(row0 + lr) * K + lk;
    const __half* bg = B + (long)(col0 + lr) * K + lk;

    auto issue = [&](int it, int buf) {
        const __half* ap = ag + it * 32;
        const __half* bp = bg + it * 32;
        const uint32_t ad = aS + buf * STAGE_B + dstOff;
        const uint32_t bd = bS + buf * STAGE_B + dstOff;
        cp16(ad, ap); cp16(ad + 16, ap + 8);
        cp16(bd, bp); cp16(bd + 16, bp + 8);
    };

    float acc[2][8][4];
#pragma unroll
    for (int i = 0; i < 2; i++)
#pragma unroll
        for (int j = 0; j < 8; j++)
#pragma unroll
            for (int e = 0; e < 4; e++) acc[i][j][e] = 0.f;

    issue(0, 0); CP_COMMIT();
    issue(1, 1); CP_COMMIT();

    const int arow = wm * 32 + (lid & 15);
    const int akof = (lid >> 4) * 8;
    const int brow = wn * 64 + (lid & 7) + (lid >> 4) * 8;
    const int bkof = ((lid >> 3) & 1) * 8;

    int buf = 0;
    for (int it = 0; it < T; ++it) {
        CP_WAIT1();
        __syncthreads();
        if (it + 2 < T) issue(it + 2, (buf + 2 >= 3) ? buf - 1 : buf + 2);
        CP_COMMIT();

        const uint32_t aBase = aS + buf * STAGE_B;
        const uint32_t bBase = bS + buf * STAGE_B;
#pragma unroll
        for (int ks = 0; ks < 2; ks++) {
            uint32_t af[2][4], bfr[4][4];
#pragma unroll
            for (int mt = 0; mt < 2; mt++)
                ldsm4(af[mt], aBase + (uint32_t)(((arow + mt * 16) * LDSR + ks * 16 + akof) * 2));
#pragma unroll
            for (int p = 0; p < 4; p++)
                ldsm4(bfr[p], bBase + (uint32_t)(((brow + p * 16) * LDSR + ks * 16 + bkof) * 2));
#pragma unroll
            for (int mt = 0; mt < 2; mt++)
#pragma unroll
                for (int nt = 0; nt < 8; nt++)
                    mma_f16(acc[mt][nt], af[mt], &bfr[nt >> 1][(nt & 1) * 2]);
        }
        buf = (buf + 1 >= 3) ? 0 : buf + 1;
    }

    const int mrow = row0 + wm * 32;
    const int ncol = col0 + wn * 64;
    const int r4 = lid >> 2, c2 = (lid & 3) * 2;
#pragma unroll
    for (int mt = 0; mt < 2; mt++) {
#pragma unroll
        for (int half = 0; half < 2; half++) {
            const long r = mrow + mt * 16 + r4 + half * 8;
#pragma unroll
            for (int nt = 0; nt < 8; nt++) {
                const int c = ncol + nt * 8 + c2;
                float v0 = acc[mt][nt][half * 2 + 0] + bias[c + 0];
                float v1 = acc[mt][nt][half * 2 + 1] + bias[c + 1];
                __half2 hh; hh.x = __float2half(v0); hh.y = __float2half(v1);
                *(__half2*)&Ch[r * N + c] = hh;
            }
        }
    }
}

// ---------------- enc GEMM (128x256 tile) + bias + LayerNorm + ReLU -> fp16 ----------------
// A = lf [16384][512] fp16, B = ent [256][512] fp16 K-major. Out h16 [16384][256].
#define EA_STAGE (128 * LDSR * 2)      // 10240
#define EB_STAGE (256 * LDSR * 2)      // 20480
#define ENC_RS   (3 * (EA_STAGE + EB_STAGE))   // 92160
#define ENC_SMEM (ENC_RS + 2048)

__global__ void __launch_bounds__(256) gemm_enc(
    const __half* __restrict__ A, const __half* __restrict__ B,
    const float* __restrict__ bias, const float* __restrict__ g,
    const float* __restrict__ beta, __half* __restrict__ Ch)
{
    extern __shared__ char smem[];
    const int tid = threadIdx.x;
    const int wid = tid >> 5, lid = tid & 31;
    const int wm = wid & 3, wn = wid >> 2;      // 4 m-groups x 2 n-groups(128 cols)
    const int row0 = blockIdx.x * 128;
    const int T = CLIPD / 32;                    // 16

    const uint32_t sBase = smem_u32(smem);
    const uint32_t aS = sBase;
    const uint32_t bS = sBase + 3 * EA_STAGE;
    float* redsm = (float*)(smem + ENC_RS);      // [128][2] sums then vars

    // loaders: A 128x32 (2 cp16/thread), B 256x32 (4 cp16/thread)
    const int lr = tid >> 1, lk = (tid & 1) * 16;
    const __half* ag = A + (long)(row0 + lr) * CLIPD + lk;
    const __half* bg = B + (long)tid * CLIPD;

    auto issue = [&](int it, int buf) {
        const __half* ap = ag + it * 32;
        const uint32_t ad = aS + buf * EA_STAGE + (uint32_t)(lr * LDSR + lk) * 2;
        cp16(ad, ap); cp16(ad + 16, ap + 8);
        const __half* bp = bg + it * 32;
        const uint32_t bd = bS + buf * EB_STAGE + (uint32_t)(tid * LDSR) * 2;
        cp16(bd, bp);      cp16(bd + 16, bp + 8);
        cp16(bd + 32, bp + 16); cp16(bd + 48, bp + 24);
    };

    float acc[2][16][4];
#pragma unroll
    for (int i = 0; i < 2; i++)
#pragma unroll
        for (int j = 0; j < 16; j++)
#pragma unroll
            for (int e = 0; e < 4; e++) acc[i][j][e] = 0.f;

    issue(0, 0); CP_COMMIT();
    issue(1, 1); CP_COMMIT();

    const int arow = wm * 32 + (lid & 15);
    const int akof = (lid >> 4) * 8;
    const int nrw = (lid & 7) + (lid >> 4) * 8;
    const int nkof = ((lid >> 3) & 1) * 8;

    int buf = 0;
    for (int it = 0; it < T; ++it) {
        CP_WAIT1();
        __syncthreads();
        if (it + 2 < T) issue(it + 2, (buf + 2 >= 3) ? buf - 1 : buf + 2);
        CP_COMMIT();

        const uint32_t aBase = aS + buf * EA_STAGE;
        const uint32_t bBase = bS + buf * EB_STAGE;
#pragma unroll
        for (int ks = 0; ks < 2; ks++) {
            uint32_t af[2][4], bfr[8][4];
#pragma unroll
            for (int mt = 0; mt < 2; mt++)
                ldsm4(af[mt], aBase + (uint32_t)(((arow + mt * 16) * LDSR + ks * 16 + akof) * 2));
#pragma unroll
            for (int p = 0; p < 8; p++)
                ldsm4(bfr[p], bBase + (uint32_t)(((wn * 128 + p * 16 + nrw) * LDSR + ks * 16 + nkof) * 2));
#pragma unroll
            for (int mt = 0; mt < 2; mt++)
#pragma unroll
                for (int nt = 0; nt < 16; nt++)
                    mma_f16(acc[mt][nt], af[mt], &bfr[nt >> 1][(nt & 1) * 2]);
        }
        buf = (buf + 1 >= 3) ? 0 : buf + 1;
    }
    __syncthreads();   // pipeline done; redsm region (aliases nothing) safe

    const int r4 = lid >> 2, c2 = (lid & 3) * 2;

    // add bias
#pragma unroll
    for (int mt = 0; mt < 2; mt++)
#pragma unroll
        for (int nt = 0; nt < 16; nt++) {
            const int c = wn * 128 + nt * 8 + c2;
            acc[mt][nt][0] += bias[c]; acc[mt][nt][1] += bias[c + 1];
            acc[mt][nt][2] += bias[c]; acc[mt][nt][3] += bias[c + 1];
        }

    // row sums (this warp's 128 cols)
    float rs[2][2];
#pragma unroll
    for (int mt = 0; mt < 2; mt++)
#pragma unroll
        for (int half = 0; half < 2; half++) {
            float s = 0.f;
#pragma unroll
            for (int nt = 0; nt < 16; nt++)
                s += acc[mt][nt][half * 2 + 0] + acc[mt][nt][half * 2 + 1];
            s += __shfl_xor_sync(0xffffffffu, s, 1);
            s += __shfl_xor_sync(0xffffffffu, s, 2);
            rs[mt][half] = s;
        }
    if ((lid & 3) == 0) {
#pragma unroll
        for (int mt = 0; mt < 2; mt++)
#pragma unroll
            for (int half = 0; half < 2; half++)
                redsm[(wm * 32 + mt * 16 + half * 8 + r4) * 2 + wn] = rs[mt][half];
    }
    __syncthreads();

    float mu[2][2];
#pragma unroll
    for (int mt = 0; mt < 2; mt++)
#pragma unroll
        for (int half = 0; half < 2; half++) {
            const int row = wm * 32 + mt * 16 + half * 8 + r4;
            mu[mt][half] = (redsm[row * 2 + 0] + redsm[row * 2 + 1]) * (1.f / 256.f);
        }

    // variance
    float* varsm = redsm + 256;
#pragma unroll
    for (int mt = 0; mt < 2; mt++)
#pragma unroll
        for (int half = 0; half < 2; half++) {
            float s = 0.f;
            const float m = mu[mt][half];
#pragma unroll
            for (int nt = 0; nt < 16; nt++) {
                float d0 = acc[mt][nt][half * 2 + 0] - m;
                float d1 = acc[mt][nt][half * 2 + 1] - m;
                s += d0 * d0 + d1 * d1;
            }
            s += __shfl_xor_sync(0xffffffffu, s, 1);
            s += __shfl_xor_sync(0xffffffffu, s, 2);
            rs[mt][half] = s;
        }
    if ((lid & 3) == 0) {
#pragma unroll
        for (int mt = 0; mt < 2; mt++)
#pragma unroll
            for (int half = 0; half < 2; half++)
                varsm[(wm * 32 + mt * 16 + half * 8 + r4) * 2 + wn] = rs[mt][half];
    }
    __syncthreads();

#pragma unroll
    for (int mt = 0; mt < 2; mt++)
#pragma unroll
        for (int half = 0; half < 2; half++) {
            const int rloc = wm * 32 + mt * 16 + half * 8 + r4;
            const float m = mu[mt][half];
            const float rstd = rsqrtf((varsm[rloc * 2 + 0] + varsm[rloc * 2 + 1]) * (1.f / 256.f) + 1e-5f);
            const long rg = row0 + rloc;
#pragma unroll
            for (int nt = 0; nt < 16; nt++) {
                const int c = wn * 128 + nt * 8 + c2;
                float v0 = fmaxf((acc[mt][nt][half * 2 + 0] - m) * rstd * g[c] + beta[c], 0.f);
                float v1 = fmaxf((acc[mt][nt][half * 2 + 1] - m) * rstd * g[c + 1] + beta[c + 1], 0.f);
                __half2 hh; hh.x = __float2half(v0); hh.y = __float2half(v1);
                *(__half2*)&Ch[rg * DD + c] = hh;
            }
        }
}

// ---------------- mega fused flash (R11 config: q-tile 128, kv-tile 64) ----------------
#define QSTR 528
#define KVTILE 33792     // 64 * 528
#define FA_QS   0
#define FA_KS0  67584
#define FA_KS1  (FA_KS0 + KVTILE)
#define FA_VS0  (FA_KS1 + KVTILE)
#define FA_VS1  (FA_VS0 + KVTILE)
#define FA_META (FA_VS1 + KVTILE)      // 202752
#define FA_BIAS (FA_META + 2048)       // 204800
#define FA_POOL (FA_BIAS + 1536)       // 206336
#define FA_SMEM (FA_POOL + 4096)       // 210432

__global__ void __launch_bounds__(256) flash_mega(
    const __half* __restrict__ qkv, const float* __restrict__ coords,
    const int* __restrict__ mask,   const float* __restrict__ gamma,
    const __half* __restrict__ bnt, const float* __restrict__ bn_b,
    const float* __restrict__ bn_g, const float* __restrict__ bn_beta,
    float* __restrict__ pp)
{
    extern __shared__ char sm[];
    const int b = blockIdx.y;
    const int q0 = blockIdx.x * 128;
    const int tid = threadIdx.x, wid = tid >> 5, lid = tid & 31;

    const uint32_t S = smem_u32(sm);
    const uint32_t Qs = S + FA_QS;
    const uint32_t KsB[2] = {S + FA_KS0, S + FA_KS1};
    const uint32_t VsB[2] = {S + FA_VS0, S + FA_VS1};
    float4* meta = (float4*)(sm + FA_META);

    {
        const int row = tid >> 1, h = tid & 1;
        const __half* src = qkv + (long)(b * NTOK + q0 + row) * QKVN + h * 128;
        const uint32_t dst = Qs + row * QSTR + h * 256;
#pragma unroll
        for (int i = 0; i < 16; i++) cp16(dst + i * 16, src + i * 8);
    }
    auto issueKV = [&](int t, int bufi) {
        const int kv0 = t * 64;
        const int row = tid >> 2, q4 = tid & 3;
        const __half* base = qkv + (long)(b * NTOK + kv0 + row) * QKVN;
        {
            const __half* src = base + 256 + q4 * 64;
            const uint32_t dst = KsB[bufi] + row * QSTR + q4 * 128;
#pragma unroll
            for (int i = 0; i < 8; i++) cp16(dst + i * 16, src + i * 8);
        }
        {
            const __half* src = base + 512 + q4 * 64;
            const uint32_t dst = VsB[bufi] + row * QSTR + q4 * 128;
#pragma unroll
            for (int i = 0; i < 8; i++) cp16(dst + i * 16, src + i * 8);
        }
    };
    auto metaStore = [&](int t, int bufi) {
        if (tid < 64) {
            const int idx = b * NTOK + t * 64 + tid;
            float2 xy = ((const float2*)coords)[idx];
            int mk = mask[idx];
            meta[bufi * 64 + tid] = make_float4(xy.x, xy.y, xy.x * xy.x + xy.y * xy.y,
                                                mk ? 0.f : 1.f);
        }
    };
    issueKV(0, 0); CP_COMMIT();
    issueKV(1, 1); CP_COMMIT();
    metaStore(0, 0);
    metaStore(1, 1);

    const int qrow = q0 + wid * 16 + (lid >> 2);
    const float ga = fabsf(gamma[0]);
    float2 c0v = ((const float2*)coords)[b * NTOK + qrow];
    float2 c1v = ((const float2*)coords)[b * NTOK + qrow + 8];
    const float xn0 = c0v.x, yn0 = c0v.y, sqn0 = c0v.x * c0v.x + c0v.y * c0v.y;
    const float xn1 = c1v.x, yn1 = c1v.y, sqn1 = c1v.x * c1v.x + c1v.y * c1v.y;

    float M0 = -INFINITY, M1 = -INFINITY, Z0 = 0.f, Z1 = 0.f;
    float o[32][4];
#pragma unroll
    for (int i = 0; i < 32; i++)
#pragma unroll
        for (int e = 0; e < 4; e++) o[i][e] = 0.f;

    const int arow = wid * 16 + (lid & 15);
    const int akof = (lid >> 4) * 8;
    const int nrw = (lid & 7) + (lid >> 4) * 8;
    const int nkof = ((lid >> 3) & 1) * 8;
    const int vrow = lid & 15;
    const int vcb  = (lid >> 4) * 16;

    for (int t = 0; t < 32; ++t) {
        const int cur = t & 1;
        CP_WAIT1();
        __syncthreads();

        float s[8][4];
#pragma unroll
        for (int j = 0; j < 8; j++)
#pragma unroll
            for (int e = 0; e < 4; e++) s[j][e] = 0.f;
        const uint32_t kb = KsB[cur];
#pragma unroll
        for (int ks = 0; ks < 16; ks++) {
            uint32_t af[4], bfr[4][4];
            ldsm4(af, Qs + (uint32_t)(arow * QSTR + (ks * 16 + akof) * 2));
#pragma unroll
            for (int p = 0; p < 4; p++)
                ldsm4(bfr[p], kb + (uint32_t)((p * 16 + nrw) * QSTR + (ks * 16 + nkof) * 2));
#pragma unroll
            for (int nt = 0; nt < 8; nt++)
                mma_f16(s[nt], af, &bfr[nt >> 1][(nt & 1) * 2]);
        }

        float mx0 = -INFINITY, mx1 = -INFINITY;
#pragma unroll
        for (int j = 0; j < 8; j++) {
            s[j][0] *= 0.0625f; s[j][1] *= 0.0625f; s[j][2] *= 0.0625f; s[j][3] *= 0.0625f;
            mx0 = fmaxf(mx0, fmaxf(s[j][0], s[j][1]));
            mx1 = fmaxf(mx1, fmaxf(s[j][2], s[j][3]));
        }
        mx0 = fmaxf(mx0, __shfl_xor_sync(0xffffffffu, mx0, 1));
        mx0 = fmaxf(mx0, __shfl_xor_sync(0xffffffffu, mx0, 2));
        mx1 = fmaxf(mx1, __shfl_xor_sync(0xffffffffu, mx1, 1));
        mx1 = fmaxf(mx1, __shfl_xor_sync(0xffffffffu, mx1, 2));
        const float Mn0 = fmaxf(M0, mx0), Mn1 = fmaxf(M1, mx1);
        const float sc0 = __expf(M0 - Mn0), sc1 = __expf(M1 - Mn1);
        M0 = Mn0; M1 = Mn1;
        Z0 *= sc0; Z1 *= sc1;
        if (sc0 != 1.f || sc1 != 1.f) {
#pragma unroll
            for (int nt = 0; nt < 32; nt++) {
                o[nt][0] *= sc0; o[nt][1] *= sc0; o[nt][2] *= sc1; o[nt][3] *= sc1;
            }
        }

        uint32_t pf[16];
        const float4* mt = meta + cur * 64;
#pragma unroll
        for (int j = 0; j < 8; j++) {
            const int cc = 8 * j + (lid & 3) * 2;
            float4 ma = mt[cc], mb = mt[cc + 1];
            float e00 = __expf(s[j][0] - Mn0), e01 = __expf(s[j][1] - Mn0);
            float e10 = __expf(s[j][2] - Mn1), e11 = __expf(s[j][3] - Mn1);
            Z0 += e00 + e01; Z1 += e10 + e11;
            float d2a0 = fmaxf(sqn0 + ma.z - 2.f * (xn0 * ma.x + yn0 * ma.y), 0.f);
            float d2b0 = fmaxf(sqn0 + mb.z - 2.f * (xn0 * mb.x + yn0 * mb.y), 0.f);
            float d2a1 = fmaxf(sqn1 + ma.z - 2.f * (xn1 * ma.x + yn1 * ma.y), 0.f);
            float d2b1 = fmaxf(sqn1 + mb.z - 2.f * (xn1 * mb.x + yn1 * mb.y), 0.f);
            float n00 = e00 * __expf(-ga * sqrtf(d2a0)) * ma.w;
            float n01 = e01 * __expf(-ga * sqrtf(d2b0)) * mb.w;
            float n10 = e10 * __expf(-ga * sqrtf(d2a1)) * ma.w;
            float n11 = e11 * __expf(-ga * sqrtf(d2b1)) * mb.w;
            __half2 p0; p0.x = __float2half(n00); p0.y = __float2half(n01);
            __half2 p1; p1.x = __float2half(n10); p1.y = __float2half(n11);
            pf[2 * j + 0] = *(uint32_t*)&p0;
            pf[2 * j + 1] = *(uint32_t*)&p1;
        }

        const uint32_t vb = VsB[cur];
#pragma unroll
        for (int ks = 0; ks < 4; ks++) {
            uint32_t a[4] = {pf[4 * ks + 0], pf[4 * ks + 1], pf[4 * ks + 2], pf[4 * ks + 3]};
            const uint32_t rowb = vb + (uint32_t)((ks * 16 + vrow) * QSTR + vcb);
#pragma unroll
            for (int p = 0; p < 16; p++) {
                uint32_t bf4[4];
                ldsm4t(bf4, rowb + (uint32_t)(p * 32));
                mma_f16(o[2 * p + 0], a, &bf4[0]);
                mma_f16(o[2 * p + 1], a, &bf4[2]);
            }
        }

        __syncthreads();
        if (t + 2 < 32) {
            issueKV(t + 2, cur); CP_COMMIT();
            metaStore(t + 2, cur);
        } else {
            CP_COMMIT();
        }
    }

    Z0 += __shfl_xor_sync(0xffffffffu, Z0, 1);
    Z0 += __shfl_xor_sync(0xffffffffu, Z0, 2);
    Z1 += __shfl_xor_sync(0xffffffffu, Z1, 1);
    Z1 += __shfl_xor_sync(0xffffffffu, Z1, 2);
    const float i0 = 1.f / Z0, i1 = 1.f / Z1;

    CP_WAIT0();
    __syncthreads();
    {
        const int row = tid >> 1, h = tid & 1;
        const __half* src = bnt + (long)row * DD + h * 128;
        const uint32_t dst = Qs + row * QSTR + h * 256;
#pragma unroll
        for (int i = 0; i < 16; i++) cp16(dst + i * 16, src + i * 8);
        CP_COMMIT();
        float* bb = (float*)(sm + FA_BIAS);
        if (tid < 128)      bb[tid] = bn_b[tid];
        else                bb[tid] = bn_g[tid - 128];
        if (tid < 128)      bb[256 + tid] = bn_beta[tid];
    }
    CP_WAIT0();
    __syncthreads();

    float acc[16][4];
#pragma unroll
    for (int nt = 0; nt < 16; nt++)
#pragma unroll
        for (int e = 0; e < 4; e++) acc[nt][e] = 0.f;

#pragma unroll
    for (int ks = 0; ks < 16; ks++) {
        __half2 t0 = __floats2half2_rn(o[2 * ks][0] * i0, o[2 * ks][1] * i0);
        __half2 t1 = __floats2half2_rn(o[2 * ks][2] * i1, o[2 * ks][3] * i1);
        __half2 t2 = __floats2half2_rn(o[2 * ks + 1][0] * i0, o[2 * ks + 1][1] * i0);
        __half2 t3 = __floats2half2_rn(o[2 * ks + 1][2] * i1, o[2 * ks + 1][3] * i1);
        uint32_t a[4] = {*(uint32_t*)&t0, *(uint32_t*)&t1, *(uint32_t*)&t2, *(uint32_t*)&t3};
#pragma unroll
        for (int p = 0; p < 8; p++) {
            uint32_t bf4[4];
            ldsm4(bf4, Qs + (uint32_t)((p * 16 + nrw) * QSTR + (ks * 16 + nkof) * 2));
            mma_f16(acc[2 * p + 0], a, &bf4[0]);
            mma_f16(acc[2 * p + 1], a, &bf4[2]);
        }
    }

    const float* bb = (const float*)(sm + FA_BIAS);
    const int cbase = (lid & 3) * 2;
    float mu0 = 0.f, mu1 = 0.f;
#pragma unroll
    for (int nt = 0; nt < 16; nt++) {
        const int c = 8 * nt + cbase;
        acc[nt][0] += bb[c]; acc[nt][1] += bb[c + 1];
        acc[nt][2] += bb[c]; acc[nt][3] += bb[c + 1];
        mu0 += acc[nt][0] + acc[nt][1];
        mu1 += acc[nt][2] + acc[nt][3];
    }
    mu0 += __shfl_xor_sync(0xffffffffu, mu0, 1);
    mu0 += __shfl_xor_sync(0xffffffffu, mu0, 2);
    mu1 += __shfl_xor_sync(0xffffffffu, mu1, 1);
    mu1 += __shfl_xor_sync(0xffffffffu, mu1, 2);
    mu0 *= (1.f / 128.f); mu1 *= (1.f / 128.f);

    float var0 = 0.f, var1 = 0.f;
#pragma unroll
    for (int nt = 0; nt < 16; nt++) {
        float d0 = acc[nt][0] - mu0, d1 = acc[nt][1] - mu0;
        float d2 = acc[nt][2] - mu1, d3 = acc[nt][3] - mu1;
        var0 += d0 * d0 + d1 * d1;
        var1 += d2 * d2 + d3 * d3;
    }
    var0 += __shfl_xor_sync(0xffffffffu, var0, 1);
    var0 += __shfl_xor_sync(0xffffffffu, var0, 2);
    var1 += __shfl_xor_sync(0xffffffffu, var1, 1);
    var1 += __shfl_xor_sync(0xffffffffu, var1, 2);
    const float rs0 = rsqrtf(var0 * (1.f / 128.f) + 1e-5f);
    const float rs1 = rsqrtf(var1 * (1.f / 128.f) + 1e-5f);

    const float m0 = mask[b * NTOK + qrow] ? 0.f : 1.f;
    const float m1 = mask[b * NTOK + qrow + 8] ? 0.f : 1.f;

    float contrib[16][2];
#pragma unroll
    for (int nt = 0; nt < 16; nt++) {
        const int c = 8 * nt + cbase;
        const float g0 = bb[128 + c], g1 = bb[128 + c + 1];
        const float be0 = bb[256 + c], be1 = bb[256 + c + 1];
        float r00 = fmaxf((acc[nt][0] - mu0) * rs0 * g0 + be0, 0.f);
        float r01 = fmaxf((acc[nt][1] - mu0) * rs0 * g1 + be1, 0.f);
        float r10 = fmaxf((acc[nt][2] - mu1) * rs1 * g0 + be0, 0.f);
        float r11 = fmaxf((acc[nt][3] - mu1) * rs1 * g1 + be1, 0.f);
        contrib[nt][0] = r00 * m0 + r10 * m1;
        contrib[nt][1] = r01 * m0 + r11 * m1;
    }
#pragma unroll
    for (int nt = 0; nt < 16; nt++) {
#pragma unroll
        for (int off = 4; off < 32; off <<= 1) {
            contrib[nt][0] += __shfl_xor_sync(0xffffffffu, contrib[nt][0], off);
            contrib[nt][1] += __shfl_xor_sync(0xffffffffu, contrib[nt][1], off);
        }
    }
    float* poolw = (float*)(sm + FA_POOL);
    if ((lid >> 2) == 0) {
#pragma unroll
        for (int nt = 0; nt < 16; nt++)
            *(float2*)&poolw[wid * 128 + 8 * nt + cbase] =
                make_float2(contrib[nt][0], contrib[nt][1]);
    }
    __syncthreads();
    if (tid < 128) {
        float s = 0.f;
#pragma unroll
        for (int w = 0; w < 8; w++) s += poolw[w * 128 + tid];
        pp[((long)b * 16 + blockIdx.x) * 128 + tid] = s;
    }
}

// ---------------- prep: weight transposes + bias concat + input convert ----------------
__device__ __forceinline__ void tr_tile(const float* __restrict__ X, __half* __restrict__ Tt,
                                        int R, int Cc, int txi, int tyi)
{
    __shared__ float t[32][33];
    const int c0 = txi * 32, r0 = tyi * 32;
    for (int i = threadIdx.y; i < 32; i += 8)
        t[i][threadIdx.x] = X[(long)(r0 + i) * Cc + c0 + threadIdx.x];
    __syncthreads();
    for (int i = threadIdx.y; i < 32; i += 8) {
        long o = (long)(c0 + i) * R + r0 + threadIdx.x;
        Tt[o] = __float2half(t[threadIdx.x][i]);
    }
}

__global__ void prep_kernel(
    const float* __restrict__ enc_w, const float* __restrict__ wq,
    const float* __restrict__ wk, const float* __restrict__ wv,
    const float* __restrict__ bn_w,
    const float* __restrict__ bq, const float* __restrict__ bk,
    const float* __restrict__ bv, const float* __restrict__ local_feat,
    __half* __restrict__ ent, __half* __restrict__ wqkvt, __half* __restrict__ bnt,
    float* __restrict__ bqkv, __half* __restrict__ lf)
{
    const int t = blockIdx.x;
    if (t < 128)        tr_tile(enc_w, ent, CLIPD, DD, t & 7, t >> 3);
    else if (t < 192) { int i = t - 128; tr_tile(wq, wqkvt,            DD, DD, i & 7, i >> 3); }
    else if (t < 256) { int i = t - 192; tr_tile(wk, wqkvt + 256 * DD, DD, DD, i & 7, i >> 3); }
    else if (t < 320) { int i = t - 256; tr_tile(wv, wqkvt + 512 * DD, DD, DD, i & 7, i >> 3); }
    else if (t < 352) { int i = t - 320; tr_tile(bn_w, bnt, DD, BDIM, i & 3, i >> 2); }
    else if (t == 352) {
        const int id = threadIdx.y * 32 + threadIdx.x;
        bqkv[id]       = bq[id];
        bqkv[256 + id] = bk[id];
        bqkv[512 + id] = bv[id];
    } else {
        const int i = (t - 353) * 256 + threadIdx.y * 32 + threadIdx.x;
        const int n4 = ROWS * CLIPD / 4;
        if (i < n4) {
            float4 v = ((const float4*)local_feat)[i];
            __half2 a; a.x = __float2half(v.x); a.y = __float2half(v.y);
            __half2 b; b.x = __float2half(v.z); b.y = __float2half(v.w);
            ((__half2*)lf)[i * 2 + 0] = a;
            ((__half2*)lf)[i * 2 + 1] = b;
        }
    }
}

// ---------------- block reduction (head) ----------------
__device__ __forceinline__ float blk_sum(float v) {
    __shared__ float sh[33];
    int lane = threadIdx.x & 31, w = threadIdx.x >> 5;
#pragma unroll
    for (int o = 16; o; o >>= 1) v += __shfl_xor_sync(0xffffffffu, v, o);
    __syncthreads();
    if (lane == 0) sh[w] = v;
    __syncthreads();
    if (threadIdx.x == 0) {
        float s = 0.f; int nw = (blockDim.x + 31) >> 5;
        for (int i = 0; i < nw; i++) s += sh[i];
        sh[32] = s;
    }
    __syncthreads();
    return sh[32];
}

// ---------------- final: pooled + head MLP ----------------
__global__ void head_kernel(const float* __restrict__ pp, const int* __restrict__ mask,
                            const float* __restrict__ c1w, const float* __restrict__ c1b,
                            const float* __restrict__ c2w, const float* __restrict__ c2b,
                            float* __restrict__ out_f)
{
    const int b = blockIdx.x;
    const int t = threadIdx.x;  // 128
    __shared__ float sp[BDIM];
    __shared__ float hid[64];

    float cf = 0.f;
    for (int n = t; n < NTOK; n += 128) cf += mask[b * NTOK + n] ? 0.f : 1.f;
    const float cnt = fmaxf(blk_sum(cf), 1e-9f);

    float s = 0.f;
#pragma unroll
    for (int ch = 0; ch < 16; ch++) s += pp[((long)b * 16 + ch) * 128 + t];
    const float pooled = s / cnt;
    out_f[BB * NCLS + b * BDIM + t] = pooled;
    sp[t] = pooled;
    __syncthreads();

    if (t < 64) {
        float h = c1b[t];
        for (int i = 0; i < BDIM; i++) h += sp[i] * c1w[i * 64 + t];
        hid[t] = fmaxf(h, 0.f);
    }
    __syncthreads();
    if (t < NCLS) {
        float l = c2b[t];
        for (int j = 0; j < 64; j++) l += hid[j] * c2w[j * NCLS + t];
        out_f[b * NCLS + t] = l;
    }
}

// ---------------- launch ----------------
extern "C" void kernel_launch(void* const* d_in, const int* in_sizes, int n_in,
                              void* d_out, int out_size)
{
    const float* local_feat = (const float*)d_in[0];
    const float* coords     = (const float*)d_in[1];
    const int*   mask       = (const int*)d_in[2];
    const float* enc_w      = (const float*)d_in[3];
    const float* enc_b      = (const float*)d_in[4];
    const float* enc_g      = (const float*)d_in[5];
    const float* enc_beta   = (const float*)d_in[6];
    const float* gamma      = (const float*)d_in[7];
    const float* wq         = (const float*)d_in[8];
    const float* bq         = (const float*)d_in[9];
    const float* wk         = (const float*)d_in[10];
    const float* bk         = (const float*)d_in[11];
    const float* wv         = (const float*)d_in[12];
    const float* bv         = (const float*)d_in[13];
    const float* bn_w       = (const float*)d_in[14];
    const float* bn_b       = (const float*)d_in[15];
    const float* bn_g       = (const float*)d_in[16];
    const float* bn_beta    = (const float*)d_in[17];
    const float* c1_w       = (const float*)d_in[18];
    const float* c1_b       = (const float*)d_in[19];
    const float* c2_w       = (const float*)d_in[20];
    const float* c2_b       = (const float*)d_in[21];

    float *pp, *bqkv;
    __half *lf, *h16, *qkv, *ent, *wqkvt, *bnt;
    cudaGetSymbolAddress((void**)&lf,    g_lf);
    cudaGetSymbolAddress((void**)&h16,   g_h16);
    cudaGetSymbolAddress((void**)&qkv,   g_qkv);
    cudaGetSymbolAddress((void**)&ent,   g_ent);
    cudaGetSymbolAddress((void**)&wqkvt, g_wqkvt);
    cudaGetSymbolAddress((void**)&bqkv,  g_bqkv);
    cudaGetSymbolAddress((void**)&bnt,   g_bnt);
    cudaGetSymbolAddress((void**)&pp,    g_pp);

    cudaFuncSetAttribute(gemm_mma,   cudaFuncAttributeMaxDynamicSharedMemorySize, GEMM_SMEM);
    cudaFuncSetAttribute(gemm_enc,   cudaFuncAttributeMaxDynamicSharedMemorySize, ENC_SMEM);
    cudaFuncSetAttribute(flash_mega, cudaFuncAttributeMaxDynamicSharedMemorySize, FA_SMEM);

    // 0) prep: transposes + bias concat + input fp16 convert (one launch)
    const int convBlocks = (ROWS * CLIPD / 4 + 255) / 256;
    prep_kernel<<<353 + convBlocks, dim3(32, 8)>>>(
        enc_w, wq, wk, wv, bn_w, bq, bk, bv, local_feat,
        ent, wqkvt, bnt, bqkv, lf);

    // 1) enc GEMM + bias + LN + relu -> h16 fp16  (M=16384, N=256, K=512)
    gemm_enc<<<ROWS / 128, 256, ENC_SMEM>>>(lf, ent, enc_b, enc_g, enc_beta, h16);

    // 2) fused qkv GEMM  (M=16384, N=768, K=256)
    gemm_mma<<<dim3(QKVN / 128, ROWS / 128), 256, GEMM_SMEM>>>(
        h16, wqkvt, qkv, QKVN, DD, bqkv);

    // 3) mega fused attention + bn + LN + pool partials
    flash_mega<<<dim3(NTOK / 128, BB), 256, FA_SMEM>>>(
        qkv, coords, mask, gamma, bnt, bn_b, bn_g, bn_beta, pp);

    // 4) pooled + head -> d_out
    head_kernel<<<BB, 128>>>(pp, mask, c1_w, c1_b, c2_w, c2_b, (float*)d_out);
}

// round 14
// speedup vs baseline: 1.5081x; 1.5081x over previous
#include <cuda_runtime.h>
#include <cuda_fp16.h>
#include <math.h>
#include <stdint.h>

#define BB 8
#define NTOK 2048
#define CLIPD 512
#define DD 256
#define BDIM 128
#define NCLS 10
#define ROWS (BB * NTOK)   // 16384
#define QKVN 768

// ---------------- scratch (no cudaMalloc allowed) ----------------
__device__ __half g_lf  [ROWS * CLIPD];
__device__ float  g_hf  [ROWS * DD];
__device__ __half g_h16 [ROWS * DD];
__device__ __half g_qkv [ROWS * QKVN];         // q | k | v fp16, row stride 768
__device__ __half g_ent [DD * CLIPD];
__device__ __half g_wqkvt[QKVN * DD];
__device__ float  g_bqkv[QKVN];
__device__ __half g_bnt [BDIM * DD];           // bn_w^T [128][256]
__device__ float  g_pp  [BB * 16 * BDIM];      // pool partials per (b, q-tile)

// ---------------- mma / ldmatrix / cp.async helpers ----------------
__device__ __forceinline__ uint32_t smem_u32(const void* p) {
    uint32_t a;
    asm("{ .reg .u64 t; cvta.to.shared.u64 t, %1; cvt.u32.u64 %0, t; }" : "=r"(a) : "l"(p));
    return a;
}
__device__ __forceinline__ void ldsm4(uint32_t* r, uint32_t addr) {
    asm volatile("ldmatrix.sync.aligned.m8n8.x4.shared.b16 {%0,%1,%2,%3}, [%4];"
                 : "=r"(r[0]), "=r"(r[1]), "=r"(r[2]), "=r"(r[3]) : "r"(addr));
}
__device__ __forceinline__ void ldsm4t(uint32_t* r, uint32_t addr) {
    asm volatile("ldmatrix.sync.aligned.m8n8.x4.trans.shared.b16 {%0,%1,%2,%3}, [%4];"
                 : "=r"(r[0]), "=r"(r[1]), "=r"(r[2]), "=r"(r[3]) : "r"(addr));
}
__device__ __forceinline__ void mma_f16(float* d, const uint32_t* a, const uint32_t* b) {
    asm volatile(
        "mma.sync.aligned.m16n8k16.row.col.f32.f16.f16.f32 "
        "{%0,%1,%2,%3}, {%4,%5,%6,%7}, {%8,%9}, {%0,%1,%2,%3};"
        : "+f"(d[0]), "+f"(d[1]), "+f"(d[2]), "+f"(d[3])
        : "r"(a[0]), "r"(a[1]), "r"(a[2]), "r"(a[3]), "r"(b[0]), "r"(b[1]));
}
__device__ __forceinline__ void cp16(uint32_t dst, const void* src) {
    asm volatile("cp.async.cg.shared.global [%0], [%1], 16;" :: "r"(dst), "l"(src));
}
#define CP_COMMIT() asm volatile("cp.async.commit_group;" ::: "memory")
#define CP_WAIT1()  asm volatile("cp.async.wait_group 1;" ::: "memory")
#define CP_WAIT0()  asm volatile("cp.async.wait_group 0;" ::: "memory")

// ---------------- fp16 HMMA GEMM, 3-stage cp.async pipeline ----------------
#define LDSR 40
#define STAGE_B (128 * LDSR * 2)
#define GEMM_SMEM (6 * STAGE_B)

template <bool HALF_OUT>
__global__ void __launch_bounds__(256) gemm_mma(
    const __half* __restrict__ A, const __half* __restrict__ B,
    float* __restrict__ C, __half* __restrict__ Ch,
    int N, int K, float alpha, const float* __restrict__ bias)
{
    extern __shared__ char smem[];
    const int tid = threadIdx.x;
    const int wid = tid >> 5, lid = tid & 31;
    const int wm = wid & 3, wn = wid >> 2;
    const int row0 = blockIdx.y * 128;
    const int col0 = blockIdx.x * 128;
    const int T = K / 32;

    const int lr = tid >> 1;
    const int lk = (tid & 1) * 16;

    const uint32_t sBase = smem_u32(smem);
    const uint32_t aS = sBase;
    const uint32_t bS = sBase + 3 * STAGE_B;
    const uint32_t dstOff = (uint32_t)(lr * LDSR + lk) * 2;

    const __half* ag = A + (long)(row0 + lr) * K + lk;
    const __half* bg = B + (long)(col0 + lr) * K + lk;

    auto issue = [&](int it, int buf) {
        const __half* ap = ag + it * 32;
        const __half* bp = bg + it * 32;
        const uint32_t ad = aS + buf * STAGE_B + dstOff;
        const uint32_t bd = bS + buf * STAGE_B + dstOff;
        cp16(ad, ap); cp16(ad + 16, ap + 8);
        cp16(bd, bp); cp16(bd + 16, bp + 8);
    };

    float acc[2][8][4];
#pragma unroll
    for (int i = 0; i < 2; i++)
#pragma unroll
        for (int j = 0; j < 8; j++)
#pragma unroll
            for (int e = 0; e < 4; e++) acc[i][j][e] = 0.f;

    issue(0, 0); CP_COMMIT();
    issue(1, 1); CP_COMMIT();

    const int arow = wm * 32 + (lid & 15);
    const int akof = (lid >> 4) * 8;
    const int brow = wn * 64 + (lid & 7) + (lid >> 4) * 8;
    const int bkof = ((lid >> 3) & 1) * 8;

    int buf = 0;
    for (int it = 0; it < T; ++it) {
        CP_WAIT1();
        __syncthreads();
        if (it + 2 < T) issue(it + 2, (buf + 2 >= 3) ? buf - 1 : buf + 2);
        CP_COMMIT();

        const uint32_t aBase = aS + buf * STAGE_B;
        const uint32_t bBase = bS + buf * STAGE_B;
#pragma unroll
        for (int ks = 0; ks < 2; ks++) {
            uint32_t af[2][4], bfr[4][4];
#pragma unroll
            for (int mt = 0; mt < 2; mt++)
                ldsm4(af[mt], aBase + (uint32_t)(((arow + mt * 16) * LDSR + ks * 16 + akof) * 2));
#pragma unroll
            for (int p = 0; p < 4; p++)
                ldsm4(bfr[p], bBase + (uint32_t)(((brow + p * 16) * LDSR + ks * 16 + bkof) * 2));
#pragma unroll
            for (int mt = 0; mt < 2; mt++)
#pragma unroll
                for (int nt = 0; nt < 8; nt++)
                    mma_f16(acc[mt][nt], af[mt], &bfr[nt >> 1][(nt & 1) * 2]);
        }
        buf = (buf + 1 >= 3) ? 0 : buf + 1;
    }

    const int mrow = row0 + wm * 32;
    const int ncol = col0 + wn * 64;
    const int r4 = lid >> 2, c2 = (lid & 3) * 2;
#pragma unroll
    for (int mt = 0; mt < 2; mt++) {
#pragma unroll
        for (int half = 0; half < 2; half++) {
            const long r = mrow + mt * 16 + r4 + half * 8;
#pragma unroll
            for (int nt = 0; nt < 8; nt++) {
                const int c = ncol + nt * 8 + c2;
                float v0 = alpha * acc[mt][nt][half * 2 + 0] + (bias ? bias[c + 0] : 0.f);
                float v1 = alpha * acc[mt][nt][half * 2 + 1] + (bias ? bias[c + 1] : 0.f);
                if (HALF_OUT) {
                    __half2 hh; hh.x = __float2half(v0); hh.y = __float2half(v1);
                    *(__half2*)&Ch[r * N + c] = hh;
                } else {
                    float2 o; o.x = v0; o.y = v1;
                    *(float2*)&C[r * N + c] = o;
                }
            }
        }
    }
}

// ---------------- mega fused flash: q-tile 128, kv-tile 64 ----------------
#define QSTR 528
#define KVTILE 33792     // 64 * 528
#define FA_QS   0
#define FA_KS0  67584
#define FA_KS1  (FA_KS0 + KVTILE)
#define FA_VS0  (FA_KS1 + KVTILE)
#define FA_VS1  (FA_VS0 + KVTILE)
#define FA_META (FA_VS1 + KVTILE)      // 202752
#define FA_BIAS (FA_META + 2048)       // 204800
#define FA_POOL (FA_BIAS + 1536)       // 206336
#define FA_SMEM (FA_POOL + 4096)       // 210432

__global__ void __launch_bounds__(256) flash_mega(
    const __half* __restrict__ qkv, const float* __restrict__ coords,
    const int* __restrict__ mask,   const float* __restrict__ gamma,
    const __half* __restrict__ bnt, const float* __restrict__ bn_b,
    const float* __restrict__ bn_g, const float* __restrict__ bn_beta,
    float* __restrict__ pp)
{
    extern __shared__ char sm[];
    const int b = blockIdx.y;
    const int q0 = blockIdx.x * 128;
    const int tid = threadIdx.x, wid = tid >> 5, lid = tid & 31;

    const uint32_t S = smem_u32(sm);
    const uint32_t Qs = S + FA_QS;
    const uint32_t KsB[2] = {S + FA_KS0, S + FA_KS1};
    const uint32_t VsB[2] = {S + FA_VS0, S + FA_VS1};
    float4* meta = (float4*)(sm + FA_META);

    {
        const int row = tid >> 1, h = tid & 1;
        const __half* src = qkv + (long)(b * NTOK + q0 + row) * QKVN + h * 128;
        const uint32_t dst = Qs + row * QSTR + h * 256;
#pragma unroll
        for (int i = 0; i < 16; i++) cp16(dst + i * 16, src + i * 8);
    }
    auto issueKV = [&](int t, int bufi) {
        const int kv0 = t * 64;
        const int row = tid >> 2, q4 = tid & 3;
        const __half* base = qkv + (long)(b * NTOK + kv0 + row) * QKVN;
        {
            const __half* src = base + 256 + q4 * 64;
            const uint32_t dst = KsB[bufi] + row * QSTR + q4 * 128;
#pragma unroll
            for (int i = 0; i < 8; i++) cp16(dst + i * 16, src + i * 8);
        }
        {
            const __half* src = base + 512 + q4 * 64;
            const uint32_t dst = VsB[bufi] + row * QSTR + q4 * 128;
#pragma unroll
            for (int i = 0; i < 8; i++) cp16(dst + i * 16, src + i * 8);
        }
    };
    auto metaStore = [&](int t, int bufi) {
        if (tid < 64) {
            const int idx = b * NTOK + t * 64 + tid;
            float2 xy = ((const float2*)coords)[idx];
            int mk = mask[idx];
            meta[bufi * 64 + tid] = make_float4(xy.x, xy.y, xy.x * xy.x + xy.y * xy.y,
                                                mk ? 0.f : 1.f);
        }
    };
    issueKV(0, 0); CP_COMMIT();
    issueKV(1, 1); CP_COMMIT();
    metaStore(0, 0);
    metaStore(1, 1);

    const int qrow = q0 + wid * 16 + (lid >> 2);
    const float ga = fabsf(gamma[0]);
    float2 c0v = ((const float2*)coords)[b * NTOK + qrow];
    float2 c1v = ((const float2*)coords)[b * NTOK + qrow + 8];
    const float xn0 = c0v.x, yn0 = c0v.y, sqn0 = c0v.x * c0v.x + c0v.y * c0v.y;
    const float xn1 = c1v.x, yn1 = c1v.y, sqn1 = c1v.x * c1v.x + c1v.y * c1v.y;

    float M0 = -INFINITY, M1 = -INFINITY, Z0 = 0.f, Z1 = 0.f;
    float o[32][4];
#pragma unroll
    for (int i = 0; i < 32; i++)
#pragma unroll
        for (int e = 0; e < 4; e++) o[i][e] = 0.f;

    const int arow = wid * 16 + (lid & 15);
    const int akof = (lid >> 4) * 8;
    const int nrw = (lid & 7) + (lid >> 4) * 8;
    const int nkof = ((lid >> 3) & 1) * 8;
    const int vrow = lid & 15;
    const int vcb  = (lid >> 4) * 16;

    for (int t = 0; t < 32; ++t) {
        const int cur = t & 1;
        CP_WAIT1();
        __syncthreads();

        float s[8][4];
#pragma unroll
        for (int j = 0; j < 8; j++)
#pragma unroll
            for (int e = 0; e < 4; e++) s[j][e] = 0.f;
        const uint32_t kb = KsB[cur];
#pragma unroll
        for (int ks = 0; ks < 16; ks++) {
            uint32_t af[4], bfr[4][4];
            ldsm4(af, Qs + (uint32_t)(arow * QSTR + (ks * 16 + akof) * 2));
#pragma unroll
            for (int p = 0; p < 4; p++)
                ldsm4(bfr[p], kb + (uint32_t)((p * 16 + nrw) * QSTR + (ks * 16 + nkof) * 2));
#pragma unroll
            for (int nt = 0; nt < 8; nt++)
                mma_f16(s[nt], af, &bfr[nt >> 1][(nt & 1) * 2]);
        }

        float mx0 = -INFINITY, mx1 = -INFINITY;
#pragma unroll
        for (int j = 0; j < 8; j++) {
            s[j][0] *= 0.0625f; s[j][1] *= 0.0625f; s[j][2] *= 0.0625f; s[j][3] *= 0.0625f;
            mx0 = fmaxf(mx0, fmaxf(s[j][0], s[j][1]));
            mx1 = fmaxf(mx1, fmaxf(s[j][2], s[j][3]));
        }
        mx0 = fmaxf(mx0, __shfl_xor_sync(0xffffffffu, mx0, 1));
        mx0 = fmaxf(mx0, __shfl_xor_sync(0xffffffffu, mx0, 2));
        mx1 = fmaxf(mx1, __shfl_xor_sync(0xffffffffu, mx1, 1));
        mx1 = fmaxf(mx1, __shfl_xor_sync(0xffffffffu, mx1, 2));
        const float Mn0 = fmaxf(M0, mx0), Mn1 = fmaxf(M1, mx1);
        const float sc0 = __expf(M0 - Mn0), sc1 = __expf(M1 - Mn1);
        M0 = Mn0; M1 = Mn1;
        Z0 *= sc0; Z1 *= sc1;
        if (sc0 != 1.f || sc1 != 1.f) {
#pragma unroll
            for (int nt = 0; nt < 32; nt++) {
                o[nt][0] *= sc0; o[nt][1] *= sc0; o[nt][2] *= sc1; o[nt][3] *= sc1;
            }
        }

        uint32_t pf[16];
        const float4* mt = meta + cur * 64;
#pragma unroll
        for (int j = 0; j < 8; j++) {
            const int cc = 8 * j + (lid & 3) * 2;
            float4 ma = mt[cc], mb = mt[cc + 1];
            float e00 = __expf(s[j][0] - Mn0), e01 = __expf(s[j][1] - Mn0);
            float e10 = __expf(s[j][2] - Mn1), e11 = __expf(s[j][3] - Mn1);
            Z0 += e00 + e01; Z1 += e10 + e11;
            float d2a0 = fmaxf(sqn0 + ma.z - 2.f * (xn0 * ma.x + yn0 * ma.y), 0.f);
            float d2b0 = fmaxf(sqn0 + mb.z - 2.f * (xn0 * mb.x + yn0 * mb.y), 0.f);
            float d2a1 = fmaxf(sqn1 + ma.z - 2.f * (xn1 * ma.x + yn1 * ma.y), 0.f);
            float d2b1 = fmaxf(sqn1 + mb.z - 2.f * (xn1 * mb.x + yn1 * mb.y), 0.f);
            float n00 = e00 * __expf(-ga * sqrtf(d2a0)) * ma.w;
            float n01 = e01 * __expf(-ga * sqrtf(d2b0)) * mb.w;
            float n10 = e10 * __expf(-ga * sqrtf(d2a1)) * ma.w;
            float n11 = e11 * __expf(-ga * sqrtf(d2b1)) * mb.w;
            __half2 p0; p0.x = __float2half(n00); p0.y = __float2half(n01);
            __half2 p1; p1.x = __float2half(n10); p1.y = __float2half(n11);
            pf[2 * j + 0] = *(uint32_t*)&p0;
            pf[2 * j + 1] = *(uint32_t*)&p1;
        }

        const uint32_t vb = VsB[cur];
#pragma unroll
        for (int ks = 0; ks < 4; ks++) {
            uint32_t a[4] = {pf[4 * ks + 0], pf[4 * ks + 1], pf[4 * ks + 2], pf[4 * ks + 3]};
            const uint32_t rowb = vb + (uint32_t)((ks * 16 + vrow) * QSTR + vcb);
#pragma unroll
            for (int p = 0; p < 16; p++) {
                uint32_t bf4[4];
                ldsm4t(bf4, rowb + (uint32_t)(p * 32));
                mma_f16(o[2 * p + 0], a, &bf4[0]);
                mma_f16(o[2 * p + 1], a, &bf4[2]);
            }
        }

        __syncthreads();
        if (t + 2 < 32) {
            issueKV(t + 2, cur); CP_COMMIT();
            metaStore(t + 2, cur);
        } else {
            CP_COMMIT();
        }
    }

    Z0 += __shfl_xor_sync(0xffffffffu, Z0, 1);
    Z0 += __shfl_xor_sync(0xffffffffu, Z0, 2);
    Z1 += __shfl_xor_sync(0xffffffffu, Z1, 1);
    Z1 += __shfl_xor_sync(0xffffffffu, Z1, 2);
    const float i0 = 1.f / Z0, i1 = 1.f / Z1;

    CP_WAIT0();
    __syncthreads();
    {
        const int row = tid >> 1, h = tid & 1;
        const __half* src = bnt + (long)row * DD + h * 128;
        const uint32_t dst = Qs + row * QSTR + h * 256;
#pragma unroll
        for (int i = 0; i < 16; i++) cp16(dst + i * 16, src + i * 8);
        CP_COMMIT();
        float* bb = (float*)(sm + FA_BIAS);
        if (tid < 128)      bb[tid] = bn_b[tid];
        else                bb[tid] = bn_g[tid - 128];
        if (tid < 128)      bb[256 + tid] = bn_beta[tid];
    }
    CP_WAIT0();
    __syncthreads();

    float acc[16][4];
#pragma unroll
    for (int nt = 0; nt < 16; nt++)
#pragma unroll
        for (int e = 0; e < 4; e++) acc[nt][e] = 0.f;

#pragma unroll
    for (int ks = 0; ks < 16; ks++) {
        __half2 t0 = __floats2half2_rn(o[2 * ks][0] * i0, o[2 * ks][1] * i0);
        __half2 t1 = __floats2half2_rn(o[2 * ks][2] * i1, o[2 * ks][3] * i1);
        __half2 t2 = __floats2half2_rn(o[2 * ks + 1][0] * i0, o[2 * ks + 1][1] * i0);
        __half2 t3 = __floats2half2_rn(o[2 * ks + 1][2] * i1, o[2 * ks + 1][3] * i1);
        uint32_t a[4] = {*(uint32_t*)&t0, *(uint32_t*)&t1, *(uint32_t*)&t2, *(uint32_t*)&t3};
#pragma unroll
        for (int p = 0; p < 8; p++) {
            uint32_t bf4[4];
            ldsm4(bf4, Qs + (uint32_t)((p * 16 + nrw) * QSTR + (ks * 16 + nkof) * 2));
            mma_f16(acc[2 * p + 0], a, &bf4[0]);
            mma_f16(acc[2 * p + 1], a, &bf4[2]);
        }
    }

    const float* bb = (const float*)(sm + FA_BIAS);
    const int cbase = (lid & 3) * 2;
    float mu0 = 0.f, mu1 = 0.f;
#pragma unroll
    for (int nt = 0; nt < 16; nt++) {
        const int c = 8 * nt + cbase;
        acc[nt][0] += bb[c]; acc[nt][1] += bb[c + 1];
        acc[nt][2] += bb[c]; acc[nt][3] += bb[c + 1];
        mu0 += acc[nt][0] + acc[nt][1];
        mu1 += acc[nt][2] + acc[nt][3];
    }
    mu0 += __shfl_xor_sync(0xffffffffu, mu0, 1);
    mu0 += __shfl_xor_sync(0xffffffffu, mu0, 2);
    mu1 += __shfl_xor_sync(0xffffffffu, mu1, 1);
    mu1 += __shfl_xor_sync(0xffffffffu, mu1, 2);
    mu0 *= (1.f / 128.f); mu1 *= (1.f / 128.f);

    float var0 = 0.f, var1 = 0.f;
#pragma unroll
    for (int nt = 0; nt < 16; nt++) {
        float d0 = acc[nt][0] - mu0, d1 = acc[nt][1] - mu0;
        float d2 = acc[nt][2] - mu1, d3 = acc[nt][3] - mu1;
        var0 += d0 * d0 + d1 * d1;
        var1 += d2 * d2 + d3 * d3;
    }
    var0 += __shfl_xor_sync(0xffffffffu, var0, 1);
    var0 += __shfl_xor_sync(0xffffffffu, var0, 2);
    var1 += __shfl_xor_sync(0xffffffffu, var1, 1);
    var1 += __shfl_xor_sync(0xffffffffu, var1, 2);
    const float rs0 = rsqrtf(var0 * (1.f / 128.f) + 1e-5f);
    const float rs1 = rsqrtf(var1 * (1.f / 128.f) + 1e-5f);

    const float m0 = mask[b * NTOK + qrow] ? 0.f : 1.f;
    const float m1 = mask[b * NTOK + qrow + 8] ? 0.f : 1.f;

    float contrib[16][2];
#pragma unroll
    for (int nt = 0; nt < 16; nt++) {
        const int c = 8 * nt + cbase;
        const float g0 = bb[128 + c], g1 = bb[128 + c + 1];
        const float be0 = bb[256 + c], be1 = bb[256 + c + 1];
        float r00 = fmaxf((acc[nt][0] - mu0) * rs0 * g0 + be0, 0.f);
        float r01 = fmaxf((acc[nt][1] - mu0) * rs0 * g1 + be1, 0.f);
        float r10 = fmaxf((acc[nt][2] - mu1) * rs1 * g0 + be0, 0.f);
        float r11 = fmaxf((acc[nt][3] - mu1) * rs1 * g1 + be1, 0.f);
        contrib[nt][0] = r00 * m0 + r10 * m1;
        contrib[nt][1] = r01 * m0 + r11 * m1;
    }
#pragma unroll
    for (int nt = 0; nt < 16; nt++) {
#pragma unroll
        for (int off = 4; off < 32; off <<= 1) {
            contrib[nt][0] += __shfl_xor_sync(0xffffffffu, contrib[nt][0], off);
            contrib[nt][1] += __shfl_xor_sync(0xffffffffu, contrib[nt][1], off);
        }
    }
    float* poolw = (float*)(sm + FA_POOL);
    if ((lid >> 2) == 0) {
#pragma unroll
        for (int nt = 0; nt < 16; nt++)
            *(float2*)&poolw[wid * 128 + 8 * nt + cbase] =
                make_float2(contrib[nt][0], contrib[nt][1]);
    }
    __syncthreads();
    if (tid < 128) {
        float s = 0.f;
#pragma unroll
        for (int w = 0; w < 8; w++) s += poolw[w * 128 + tid];
        pp[((long)b * 16 + blockIdx.x) * 128 + tid] = s;
    }
}

// ---------------- prep: weight transposes + bias concat + input convert ----------------
__device__ __forceinline__ void tr_tile(const float* __restrict__ X, __half* __restrict__ Tt,
                                        int R, int Cc, int txi, int tyi)
{
    __shared__ float t[32][33];
    const int c0 = txi * 32, r0 = tyi * 32;
    for (int i = threadIdx.y; i < 32; i += 8)
        t[i][threadIdx.x] = X[(long)(r0 + i) * Cc + c0 + threadIdx.x];
    __syncthreads();
    for (int i = threadIdx.y; i < 32; i += 8) {
        long o = (long)(c0 + i) * R + r0 + threadIdx.x;
        Tt[o] = __float2half(t[threadIdx.x][i]);
    }
}

__global__ void prep_kernel(
    const float* __restrict__ enc_w, const float* __restrict__ wq,
    const float* __restrict__ wk, const float* __restrict__ wv,
    const float* __restrict__ bn_w,
    const float* __restrict__ bq, const float* __restrict__ bk,
    const float* __restrict__ bv, const float* __restrict__ local_feat,
    __half* __restrict__ ent, __half* __restrict__ wqkvt, __half* __restrict__ bnt,
    float* __restrict__ bqkv, __half* __restrict__ lf)
{
    const int t = blockIdx.x;
    if (t < 128)        tr_tile(enc_w, ent, CLIPD, DD, t & 7, t >> 3);
    else if (t < 192) { int i = t - 128; tr_tile(wq, wqkvt,            DD, DD, i & 7, i >> 3); }
    else if (t < 256) { int i = t - 192; tr_tile(wk, wqkvt + 256 * DD, DD, DD, i & 7, i >> 3); }
    else if (t < 320) { int i = t - 256; tr_tile(wv, wqkvt + 512 * DD, DD, DD, i & 7, i >> 3); }
    else if (t < 352) { int i = t - 320; tr_tile(bn_w, bnt, DD, BDIM, i & 3, i >> 2); }
    else if (t == 352) {
        const int id = threadIdx.y * 32 + threadIdx.x;
        bqkv[id]       = bq[id];
        bqkv[256 + id] = bk[id];
        bqkv[512 + id] = bv[id];
    } else {
        const int i = (t - 353) * 256 + threadIdx.y * 32 + threadIdx.x;
        const int n4 = ROWS * CLIPD / 4;
        if (i < n4) {
            float4 v = ((const float4*)local_feat)[i];
            __half2 a; a.x = __float2half(v.x); a.y = __float2half(v.y);
            __half2 b; b.x = __float2half(v.z); b.y = __float2half(v.w);
            ((__half2*)lf)[i * 2 + 0] = a;
            ((__half2*)lf)[i * 2 + 1] = b;
        }
    }
}

// ---------------- warp-per-row LayerNorm + ReLU (D=256) ----------------
__global__ void __launch_bounds__(256) ln_relu_kernel(
    const float* __restrict__ X, const float* __restrict__ g,
    const float* __restrict__ beta, __half* __restrict__ h16)
{
    const int wid = threadIdx.x >> 5, lid = threadIdx.x & 31;
    const long row = (long)blockIdx.x * 8 + wid;
    const float4* xr = (const float4*)(X + row * DD);
    float4 v0 = xr[lid], v1 = xr[lid + 32];

    float s = v0.x + v0.y + v0.z + v0.w + v1.x + v1.y + v1.z + v1.w;
#pragma unroll
    for (int o = 16; o; o >>= 1) s += __shfl_xor_sync(0xffffffffu, s, o);
    const float mu = s * (1.f / 256.f);

    float d0x = v0.x - mu, d0y = v0.y - mu, d0z = v0.z - mu, d0w = v0.w - mu;
    float d1x = v1.x - mu, d1y = v1.y - mu, d1z = v1.z - mu, d1w = v1.w - mu;
    float vs = d0x * d0x + d0y * d0y + d0z * d0z + d0w * d0w
             + d1x * d1x + d1y * d1y + d1z * d1z + d1w * d1w;
#pragma unroll
    for (int o = 16; o; o >>= 1) vs += __shfl_xor_sync(0xffffffffu, vs, o);
    const float rstd = rsqrtf(vs * (1.f / 256.f) + 1e-5f);

    float4 g0 = ((const float4*)g)[lid],    g1 = ((const float4*)g)[lid + 32];
    float4 b0 = ((const float4*)beta)[lid], b1 = ((const float4*)beta)[lid + 32];

    __half2 h0, h1, h2, h3;
    h0.x = __float2half(fmaxf(d0x * rstd * g0.x + b0.x, 0.f));
    h0.y = __float2half(fmaxf(d0y * rstd * g0.y + b0.y, 0.f));
    h1.x = __float2half(fmaxf(d0z * rstd * g0.z + b0.z, 0.f));
    h1.y = __float2half(fmaxf(d0w * rstd * g0.w + b0.w, 0.f));
    h2.x = __float2half(fmaxf(d1x * rstd * g1.x + b1.x, 0.f));
    h2.y = __float2half(fmaxf(d1y * rstd * g1.y + b1.y, 0.f));
    h3.x = __float2half(fmaxf(d1z * rstd * g1.z + b1.z, 0.f));
    h3.y = __float2half(fmaxf(d1w * rstd * g1.w + b1.w, 0.f));
    __half2* yr = (__half2*)(h16 + row * DD);
    yr[lid * 2 + 0] = h0; yr[lid * 2 + 1] = h1;
    yr[64 + lid * 2 + 0] = h2; yr[64 + lid * 2 + 1] = h3;
}

// ---------------- block reduction (head) ----------------
__device__ __forceinline__ float blk_sum(float v) {
    __shared__ float sh[33];
    int lane = threadIdx.x & 31, w = threadIdx.x >> 5;
#pragma unroll
    for (int o = 16; o; o >>= 1) v += __shfl_xor_sync(0xffffffffu, v, o);
    __syncthreads();
    if (lane == 0) sh[w] = v;
    __syncthreads();
    if (threadIdx.x == 0) {
        float s = 0.f; int nw = (blockDim.x + 31) >> 5;
        for (int i = 0; i < nw; i++) s += sh[i];
        sh[32] = s;
    }
    __syncthreads();
    return sh[32];
}

// ---------------- final: pooled + head MLP ----------------
__global__ void head_kernel(const float* __restrict__ pp, const int* __restrict__ mask,
                            const float* __restrict__ c1w, const float* __restrict__ c1b,
                            const float* __restrict__ c2w, const float* __restrict__ c2b,
                            float* __restrict__ out_f)
{
    const int b = blockIdx.x;
    const int t = threadIdx.x;  // 128
    __shared__ float sp[BDIM];
    __shared__ float hid[64];

    float cf = 0.f;
    for (int n = t; n < NTOK; n += 128) cf += mask[b * NTOK + n] ? 0.f : 1.f;
    const float cnt = fmaxf(blk_sum(cf), 1e-9f);

    float s = 0.f;
#pragma unroll
    for (int ch = 0; ch < 16; ch++) s += pp[((long)b * 16 + ch) * 128 + t];
    const float pooled = s / cnt;
    out_f[BB * NCLS + b * BDIM + t] = pooled;
    sp[t] = pooled;
    __syncthreads();

    if (t < 64) {
        float h = c1b[t];
        for (int i = 0; i < BDIM; i++) h += sp[i] * c1w[i * 64 + t];
        hid[t] = fmaxf(h, 0.f);
    }
    __syncthreads();
    if (t < NCLS) {
        float l = c2b[t];
        for (int j = 0; j < 64; j++) l += hid[j] * c2w[j * NCLS + t];
        out_f[b * NCLS + t] = l;
    }
}

// ---------------- launch ----------------
extern "C" void kernel_launch(void* const* d_in, const int* in_sizes, int n_in,
                              void* d_out, int out_size)
{
    const float* local_feat = (const float*)d_in[0];
    const float* coords     = (const float*)d_in[1];
    const int*   mask       = (const int*)d_in[2];
    const float* enc_w      = (const float*)d_in[3];
    const float* enc_b      = (const float*)d_in[4];
    const float* enc_g      = (const float*)d_in[5];
    const float* enc_beta   = (const float*)d_in[6];
    const float* gamma      = (const float*)d_in[7];
    const float* wq         = (const float*)d_in[8];
    const float* bq         = (const float*)d_in[9];
    const float* wk         = (const float*)d_in[10];
    const float* bk         = (const float*)d_in[11];
    const float* wv         = (const float*)d_in[12];
    const float* bv         = (const float*)d_in[13];
    const float* bn_w       = (const float*)d_in[14];
    const float* bn_b       = (const float*)d_in[15];
    const float* bn_g       = (const float*)d_in[16];
    const float* bn_beta    = (const float*)d_in[17];
    const float* c1_w       = (const float*)d_in[18];
    const float* c1_b       = (const float*)d_in[19];
    const float* c2_w       = (const float*)d_in[20];
    const float* c2_b       = (const float*)d_in[21];

    float *hf, *pp, *bqkv;
    __half *lf, *h16, *qkv, *ent, *wqkvt, *bnt;
    cudaGetSymbolAddress((void**)&lf,    g_lf);
    cudaGetSymbolAddress((void**)&hf,    g_hf);
    cudaGetSymbolAddress((void**)&h16,   g_h16);
    cudaGetSymbolAddress((void**)&qkv,   g_qkv);
    cudaGetSymbolAddress((void**)&ent,   g_ent);
    cudaGetSymbolAddress((void**)&wqkvt, g_wqkvt);
    cudaGetSymbolAddress((void**)&bqkv,  g_bqkv);
    cudaGetSymbolAddress((void**)&bnt,   g_bnt);
    cudaGetSymbolAddress((void**)&pp,    g_pp);

    cudaFuncSetAttribute(gemm_mma<false>, cudaFuncAttributeMaxDynamicSharedMemorySize, GEMM_SMEM);
    cudaFuncSetAttribute(gemm_mma<true>,  cudaFuncAttributeMaxDynamicSharedMemorySize, GEMM_SMEM);
    cudaFuncSetAttribute(flash_mega,      cudaFuncAttributeMaxDynamicSharedMemorySize, FA_SMEM);

    // 0) prep: transposes + bias concat + input fp16 convert (one launch)
    const int convBlocks = (ROWS * CLIPD / 4 + 255) / 256;
    prep_kernel<<<353 + convBlocks, dim3(32, 8)>>>(
        enc_w, wq, wk, wv, bn_w, bq, bk, bv, local_feat,
        ent, wqkvt, bnt, bqkv, lf);

    // 1) enc GEMM + LN
    gemm_mma<false><<<dim3(DD / 128, ROWS / 128), 256, GEMM_SMEM>>>(
        lf, ent, hf, nullptr, DD, CLIPD, 1.f, enc_b);
    ln_relu_kernel<<<ROWS / 8, 256>>>(hf, enc_g, enc_beta, h16);

    // 2) fused qkv GEMM  (M=16384, N=768, K=256)
    gemm_mma<true><<<dim3(QKVN / 128, ROWS / 128), 256, GEMM_SMEM>>>(
        h16, wqkvt, nullptr, qkv, QKVN, DD, 1.f, bqkv);

    // 3) mega fused attention + bn + LN + pool partials
    flash_mega<<<dim3(NTOK / 128, BB), 256, FA_SMEM>>>(
        qkv, coords, mask, gamma, bnt, bn_b, bn_g, bn_beta, pp);

    // 4) pooled + head -> d_out
    head_kernel<<<BB, 128>>>(pp, mask, c1_w, c1_b, c2_w, c2_b, (float*)d_out);
}

// round 15
// speedup vs baseline: 1.7267x; 1.1449x over previous
#include <cuda_runtime.h>
#include <cuda_fp16.h>
#include <math.h>
#include <stdint.h>

#define BB 8
#define NTOK 2048
#define CLIPD 512
#define DD 256
#define BDIM 128
#define NCLS 10
#define ROWS (BB * NTOK)   // 16384
#define QKVN 768

// ---------------- scratch (no cudaMalloc allowed) ----------------
__device__ __half g_lf  [ROWS * CLIPD];
__device__ float  g_hf  [ROWS * DD];
__device__ __half g_h16 [ROWS * DD];
__device__ __half g_qkv [ROWS * QKVN];         // q | k | v fp16, row stride 768 (q pre-scaled by 1/16)
__device__ __half g_ent [DD * CLIPD];
__device__ __half g_wqkvt[QKVN * DD];
__device__ float  g_bqkv[QKVN];
__device__ __half g_bnt [BDIM * DD];           // bn_w^T [128][256]
__device__ float  g_pp  [BB * 16 * BDIM];      // pool partials per (b, q-tile)

// ---------------- mma / ldmatrix / cp.async helpers ----------------
__device__ __forceinline__ uint32_t smem_u32(const void* p) {
    uint32_t a;
    asm("{ .reg .u64 t; cvta.to.shared.u64 t, %1; cvt.u32.u64 %0, t; }" : "=r"(a) : "l"(p));
    return a;
}
__device__ __forceinline__ void ldsm4(uint32_t* r, uint32_t addr) {
    asm volatile("ldmatrix.sync.aligned.m8n8.x4.shared.b16 {%0,%1,%2,%3}, [%4];"
                 : "=r"(r[0]), "=r"(r[1]), "=r"(r[2]), "=r"(r[3]) : "r"(addr));
}
__device__ __forceinline__ void ldsm4t(uint32_t* r, uint32_t addr) {
    asm volatile("ldmatrix.sync.aligned.m8n8.x4.trans.shared.b16 {%0,%1,%2,%3}, [%4];"
                 : "=r"(r[0]), "=r"(r[1]), "=r"(r[2]), "=r"(r[3]) : "r"(addr));
}
__device__ __forceinline__ void mma_f16(float* d, const uint32_t* a, const uint32_t* b) {
    asm volatile(
        "mma.sync.aligned.m16n8k16.row.col.f32.f16.f16.f32 "
        "{%0,%1,%2,%3}, {%4,%5,%6,%7}, {%8,%9}, {%0,%1,%2,%3};"
        : "+f"(d[0]), "+f"(d[1]), "+f"(d[2]), "+f"(d[3])
        : "r"(a[0]), "r"(a[1]), "r"(a[2]), "r"(a[3]), "r"(b[0]), "r"(b[1]));
}
__device__ __forceinline__ void cp16(uint32_t dst, const void* src) {
    asm volatile("cp.async.cg.shared.global [%0], [%1], 16;" :: "r"(dst), "l"(src));
}
#define CP_COMMIT() asm volatile("cp.async.commit_group;" ::: "memory")
#define CP_WAIT1()  asm volatile("cp.async.wait_group 1;" ::: "memory")
#define CP_WAIT0()  asm volatile("cp.async.wait_group 0;" ::: "memory")

// ---------------- fp16 HMMA GEMM, 3-stage cp.async pipeline ----------------
#define LDSR 40
#define STAGE_B (128 * LDSR * 2)
#define GEMM_SMEM (6 * STAGE_B)

template <bool HALF_OUT>
__global__ void __launch_bounds__(256) gemm_mma(
    const __half* __restrict__ A, const __half* __restrict__ B,
    float* __restrict__ C, __half* __restrict__ Ch,
    int N, int K, float alpha, const float* __restrict__ bias)
{
    extern __shared__ char smem[];
    const int tid = threadIdx.x;
    const int wid = tid >> 5, lid = tid & 31;
    const int wm = wid & 3, wn = wid >> 2;
    const int row0 = blockIdx.y * 128;
    const int col0 = blockIdx.x * 128;
    const int T = K / 32;

    const int lr = tid >> 1;
    const int lk = (tid & 1) * 16;

    const uint32_t sBase = smem_u32(smem);
    const uint32_t aS = sBase;
    const uint32_t bS = sBase + 3 * STAGE_B;
    const uint32_t dstOff = (uint32_t)(lr * LDSR + lk) * 2;

    const __half* ag = A + (long)(row0 + lr) * K + lk;
    const __half* bg = B + (long)(col0 + lr) * K + lk;

    auto issue = [&](int it, int buf) {
        const __half* ap = ag + it * 32;
        const __half* bp = bg + it * 32;
        const uint32_t ad = aS + buf * STAGE_B + dstOff;
        const uint32_t bd = bS + buf * STAGE_B + dstOff;
        cp16(ad, ap); cp16(ad + 16, ap + 8);
        cp16(bd, bp); cp16(bd + 16, bp + 8);
    };

    float acc[2][8][4];
#pragma unroll
    for (int i = 0; i < 2; i++)
#pragma unroll
        for (int j = 0; j < 8; j++)
#pragma unroll
            for (int e = 0; e < 4; e++) acc[i][j][e] = 0.f;

    issue(0, 0); CP_COMMIT();
    issue(1, 1); CP_COMMIT();

    const int arow = wm * 32 + (lid & 15);
    const int akof = (lid >> 4) * 8;
    const int brow = wn * 64 + (lid & 7) + (lid >> 4) * 8;
    const int bkof = ((lid >> 3) & 1) * 8;

    int buf = 0;
    for (int it = 0; it < T; ++it) {
        CP_WAIT1();
        __syncthreads();
        if (it + 2 < T) issue(it + 2, (buf + 2 >= 3) ? buf - 1 : buf + 2);
        CP_COMMIT();

        const uint32_t aBase = aS + buf * STAGE_B;
        const uint32_t bBase = bS + buf * STAGE_B;
#pragma unroll
        for (int ks = 0; ks < 2; ks++) {
            uint32_t af[2][4], bfr[4][4];
#pragma unroll
            for (int mt = 0; mt < 2; mt++)
                ldsm4(af[mt], aBase + (uint32_t)(((arow + mt * 16) * LDSR + ks * 16 + akof) * 2));
#pragma unroll
            for (int p = 0; p < 4; p++)
                ldsm4(bfr[p], bBase + (uint32_t)(((brow + p * 16) * LDSR + ks * 16 + bkof) * 2));
#pragma unroll
            for (int mt = 0; mt < 2; mt++)
#pragma unroll
                for (int nt = 0; nt < 8; nt++)
                    mma_f16(acc[mt][nt], af[mt], &bfr[nt >> 1][(nt & 1) * 2]);
        }
        buf = (buf + 1 >= 3) ? 0 : buf + 1;
    }

    const int mrow = row0 + wm * 32;
    const int ncol = col0 + wn * 64;
    const int r4 = lid >> 2, c2 = (lid & 3) * 2;
#pragma unroll
    for (int mt = 0; mt < 2; mt++) {
#pragma unroll
        for (int half = 0; half < 2; half++) {
            const long r = mrow + mt * 16 + r4 + half * 8;
#pragma unroll
            for (int nt = 0; nt < 8; nt++) {
                const int c = ncol + nt * 8 + c2;
                float v0 = alpha * acc[mt][nt][half * 2 + 0] + (bias ? bias[c + 0] : 0.f);
                float v1 = alpha * acc[mt][nt][half * 2 + 1] + (bias ? bias[c + 1] : 0.f);
                if (HALF_OUT) {
                    __half2 hh; hh.x = __float2half(v0); hh.y = __float2half(v1);
                    *(__half2*)&Ch[r * N + c] = hh;
                } else {
                    float2 o; o.x = v0; o.y = v1;
                    *(float2*)&C[r * N + c] = o;
                }
            }
        }
    }
}

// ---------------- mega fused flash: q-tile 128, kv-tile 64 ----------------
// q is pre-scaled by 1/sqrt(D) at the weight level, so S needs no scaling here.
#define QSTR 528
#define KVTILE 33792     // 64 * 528
#define FA_QS   0
#define FA_KS0  67584
#define FA_KS1  (FA_KS0 + KVTILE)
#define FA_VS0  (FA_KS1 + KVTILE)
#define FA_VS1  (FA_VS0 + KVTILE)
#define FA_META (FA_VS1 + KVTILE)      // 202752
#define FA_BIAS (FA_META + 2048)       // 204800
#define FA_POOL (FA_BIAS + 1536)       // 206336
#define FA_SMEM (FA_POOL + 4096)       // 210432

__global__ void __launch_bounds__(256) flash_mega(
    const __half* __restrict__ qkv, const float* __restrict__ coords,
    const int* __restrict__ mask,   const float* __restrict__ gamma,
    const __half* __restrict__ bnt, const float* __restrict__ bn_b,
    const float* __restrict__ bn_g, const float* __restrict__ bn_beta,
    float* __restrict__ pp)
{
    extern __shared__ char sm[];
    const int b = blockIdx.y;
    const int q0 = blockIdx.x * 128;
    const int tid = threadIdx.x, wid = tid >> 5, lid = tid & 31;

    const uint32_t S = smem_u32(sm);
    const uint32_t Qs = S + FA_QS;
    const uint32_t KsB[2] = {S + FA_KS0, S + FA_KS1};
    const uint32_t VsB[2] = {S + FA_VS0, S + FA_VS1};
    float4* meta = (float4*)(sm + FA_META);

    {
        const int row = tid >> 1, h = tid & 1;
        const __half* src = qkv + (long)(b * NTOK + q0 + row) * QKVN + h * 128;
        const uint32_t dst = Qs + row * QSTR + h * 256;
#pragma unroll
        for (int i = 0; i < 16; i++) cp16(dst + i * 16, src + i * 8);
    }
    auto issueKV = [&](int t, int bufi) {
        const int kv0 = t * 64;
        const int row = tid >> 2, q4 = tid & 3;
        const __half* base = qkv + (long)(b * NTOK + kv0 + row) * QKVN;
        {
            const __half* src = base + 256 + q4 * 64;
            const uint32_t dst = KsB[bufi] + row * QSTR + q4 * 128;
#pragma unroll
            for (int i = 0; i < 8; i++) cp16(dst + i * 16, src + i * 8);
        }
        {
            const __half* src = base + 512 + q4 * 64;
            const uint32_t dst = VsB[bufi] + row * QSTR + q4 * 128;
#pragma unroll
            for (int i = 0; i < 8; i++) cp16(dst + i * 16, src + i * 8);
        }
    };
    auto metaStore = [&](int t, int bufi) {
        if (tid < 64) {
            const int idx = b * NTOK + t * 64 + tid;
            float2 xy = ((const float2*)coords)[idx];
            int mk = mask[idx];
            meta[bufi * 64 + tid] = make_float4(xy.x, xy.y, xy.x * xy.x + xy.y * xy.y,
                                                mk ? 0.f : 1.f);
        }
    };
    issueKV(0, 0); CP_COMMIT();
    issueKV(1, 1); CP_COMMIT();
    metaStore(0, 0);
    metaStore(1, 1);

    const int qrow = q0 + wid * 16 + (lid >> 2);
    const float ga = fabsf(gamma[0]);
    float2 c0v = ((const float2*)coords)[b * NTOK + qrow];
    float2 c1v = ((const float2*)coords)[b * NTOK + qrow + 8];
    const float xn0 = c0v.x, yn0 = c0v.y, sqn0 = c0v.x * c0v.x + c0v.y * c0v.y;
    const float xn1 = c1v.x, yn1 = c1v.y, sqn1 = c1v.x * c1v.x + c1v.y * c1v.y;

    float M0 = -INFINITY, M1 = -INFINITY, Z0 = 0.f, Z1 = 0.f;
    float o[32][4];
#pragma unroll
    for (int i = 0; i < 32; i++)
#pragma unroll
        for (int e = 0; e < 4; e++) o[i][e] = 0.f;

    const int arow = wid * 16 + (lid & 15);
    const int akof = (lid >> 4) * 8;
    const int nrw = (lid & 7) + (lid >> 4) * 8;
    const int nkof = ((lid >> 3) & 1) * 8;
    const int vrow = lid & 15;
    const int vcb  = (lid >> 4) * 16;

    for (int t = 0; t < 32; ++t) {
        const int cur = t & 1;
        CP_WAIT1();
        __syncthreads();

        float s[8][4];
#pragma unroll
        for (int j = 0; j < 8; j++)
#pragma unroll
            for (int e = 0; e < 4; e++) s[j][e] = 0.f;
        const uint32_t kb = KsB[cur];
#pragma unroll
        for (int ks = 0; ks < 16; ks++) {
            uint32_t af[4], bfr[4][4];
            ldsm4(af, Qs + (uint32_t)(arow * QSTR + (ks * 16 + akof) * 2));
#pragma unroll
            for (int p = 0; p < 4; p++)
                ldsm4(bfr[p], kb + (uint32_t)((p * 16 + nrw) * QSTR + (ks * 16 + nkof) * 2));
#pragma unroll
            for (int nt = 0; nt < 8; nt++)
                mma_f16(s[nt], af, &bfr[nt >> 1][(nt & 1) * 2]);
        }

        // ---- online softmax (S already pre-scaled by 1/16 via q weights) ----
        float mx0 = -INFINITY, mx1 = -INFINITY;
#pragma unroll
        for (int j = 0; j < 8; j++) {
            mx0 = fmaxf(mx0, fmaxf(s[j][0], s[j][1]));
            mx1 = fmaxf(mx1, fmaxf(s[j][2], s[j][3]));
        }
        mx0 = fmaxf(mx0, __shfl_xor_sync(0xffffffffu, mx0, 1));
        mx0 = fmaxf(mx0, __shfl_xor_sync(0xffffffffu, mx0, 2));
        mx1 = fmaxf(mx1, __shfl_xor_sync(0xffffffffu, mx1, 1));
        mx1 = fmaxf(mx1, __shfl_xor_sync(0xffffffffu, mx1, 2));
        const float Mn0 = fmaxf(M0, mx0), Mn1 = fmaxf(M1, mx1);
        const float sc0 = __expf(M0 - Mn0), sc1 = __expf(M1 - Mn1);
        M0 = Mn0; M1 = Mn1;
        Z0 *= sc0; Z1 *= sc1;
        if (sc0 != 1.f || sc1 != 1.f) {
#pragma unroll
            for (int nt = 0; nt < 32; nt++) {
                o[nt][0] *= sc0; o[nt][1] *= sc0; o[nt][2] *= sc1; o[nt][3] *= sc1;
            }
        }

        uint32_t pf[16];
        const float4* mt = meta + cur * 64;
#pragma unroll
        for (int j = 0; j < 8; j++) {
            const int cc = 8 * j + (lid & 3) * 2;
            float4 ma = mt[cc], mb = mt[cc + 1];
            float e00 = __expf(s[j][0] - Mn0), e01 = __expf(s[j][1] - Mn0);
            float e10 = __expf(s[j][2] - Mn1), e11 = __expf(s[j][3] - Mn1);
            Z0 += e00 + e01; Z1 += e10 + e11;
            float d2a0 = fmaxf(sqn0 + ma.z - 2.f * (xn0 * ma.x + yn0 * ma.y), 0.f);
            float d2b0 = fmaxf(sqn0 + mb.z - 2.f * (xn0 * mb.x + yn0 * mb.y), 0.f);
            float d2a1 = fmaxf(sqn1 + ma.z - 2.f * (xn1 * ma.x + yn1 * ma.y), 0.f);
            float d2b1 = fmaxf(sqn1 + mb.z - 2.f * (xn1 * mb.x + yn1 * mb.y), 0.f);
            // dist = sqrt(d2) via single MUFU.RSQ: d2 * rsqrt(d2); exact 0 for d2 = 0.
            float da0 = d2a0 * rsqrtf(fmaxf(d2a0, 1e-20f));
            float db0 = d2b0 * rsqrtf(fmaxf(d2b0, 1e-20f));
            float da1 = d2a1 * rsqrtf(fmaxf(d2a1, 1e-20f));
            float db1 = d2b1 * rsqrtf(fmaxf(d2b1, 1e-20f));
            float n00 = e00 * __expf(-ga * da0) * ma.w;
            float n01 = e01 * __expf(-ga * db0) * mb.w;
            float n10 = e10 * __expf(-ga * da1) * ma.w;
            float n11 = e11 * __expf(-ga * db1) * mb.w;
            __half2 p0; p0.x = __float2half(n00); p0.y = __float2half(n01);
            __half2 p1; p1.x = __float2half(n10); p1.y = __float2half(n11);
            pf[2 * j + 0] = *(uint32_t*)&p0;
            pf[2 * j + 1] = *(uint32_t*)&p1;
        }

        const uint32_t vb = VsB[cur];
#pragma unroll
        for (int ks = 0; ks < 4; ks++) {
            uint32_t a[4] = {pf[4 * ks + 0], pf[4 * ks + 1], pf[4 * ks + 2], pf[4 * ks + 3]};
            const uint32_t rowb = vb + (uint32_t)((ks * 16 + vrow) * QSTR + vcb);
#pragma unroll
            for (int p = 0; p < 16; p++) {
                uint32_t bf4[4];
                ldsm4t(bf4, rowb + (uint32_t)(p * 32));
                mma_f16(o[2 * p + 0], a, &bf4[0]);
                mma_f16(o[2 * p + 1], a, &bf4[2]);
            }
        }

        __syncthreads();
        if (t + 2 < 32) {
            issueKV(t + 2, cur); CP_COMMIT();
            metaStore(t + 2, cur);
        } else {
            CP_COMMIT();
        }
    }

    Z0 += __shfl_xor_sync(0xffffffffu, Z0, 1);
    Z0 += __shfl_xor_sync(0xffffffffu, Z0, 2);
    Z1 += __shfl_xor_sync(0xffffffffu, Z1, 1);
    Z1 += __shfl_xor_sync(0xffffffffu, Z1, 2);
    const float i0 = 1.f / Z0, i1 = 1.f / Z1;

    CP_WAIT0();
    __syncthreads();
    {
        const int row = tid >> 1, h = tid & 1;
        const __half* src = bnt + (long)row * DD + h * 128;
        const uint32_t dst = Qs + row * QSTR + h * 256;
#pragma unroll
        for (int i = 0; i < 16; i++) cp16(dst + i * 16, src + i * 8);
        CP_COMMIT();
        float* bb = (float*)(sm + FA_BIAS);
        if (tid < 128)      bb[tid] = bn_b[tid];
        else                bb[tid] = bn_g[tid - 128];
        if (tid < 128)      bb[256 + tid] = bn_beta[tid];
    }
    CP_WAIT0();
    __syncthreads();

    float acc[16][4];
#pragma unroll
    for (int nt = 0; nt < 16; nt++)
#pragma unroll
        for (int e = 0; e < 4; e++) acc[nt][e] = 0.f;

#pragma unroll
    for (int ks = 0; ks < 16; ks++) {
        __half2 t0 = __floats2half2_rn(o[2 * ks][0] * i0, o[2 * ks][1] * i0);
        __half2 t1 = __floats2half2_rn(o[2 * ks][2] * i1, o[2 * ks][3] * i1);
        __half2 t2 = __floats2half2_rn(o[2 * ks + 1][0] * i0, o[2 * ks + 1][1] * i0);
        __half2 t3 = __floats2half2_rn(o[2 * ks + 1][2] * i1, o[2 * ks + 1][3] * i1);
        uint32_t a[4] = {*(uint32_t*)&t0, *(uint32_t*)&t1, *(uint32_t*)&t2, *(uint32_t*)&t3};
#pragma unroll
        for (int p = 0; p < 8; p++) {
            uint32_t bf4[4];
            ldsm4(bf4, Qs + (uint32_t)((p * 16 + nrw) * QSTR + (ks * 16 + nkof) * 2));
            mma_f16(acc[2 * p + 0], a, &bf4[0]);
            mma_f16(acc[2 * p + 1], a, &bf4[2]);
        }
    }

    const float* bb = (const float*)(sm + FA_BIAS);
    const int cbase = (lid & 3) * 2;
    float mu0 = 0.f, mu1 = 0.f;
#pragma unroll
    for (int nt = 0; nt < 16; nt++) {
        const int c = 8 * nt + cbase;
        acc[nt][0] += bb[c]; acc[nt][1] += bb[c + 1];
        acc[nt][2] += bb[c]; acc[nt][3] += bb[c + 1];
        mu0 += acc[nt][0] + acc[nt][1];
        mu1 += acc[nt][2] + acc[nt][3];
    }
    mu0 += __shfl_xor_sync(0xffffffffu, mu0, 1);
    mu0 += __shfl_xor_sync(0xffffffffu, mu0, 2);
    mu1 += __shfl_xor_sync(0xffffffffu, mu1, 1);
    mu1 += __shfl_xor_sync(0xffffffffu, mu1, 2);
    mu0 *= (1.f / 128.f); mu1 *= (1.f / 128.f);

    float var0 = 0.f, var1 = 0.f;
#pragma unroll
    for (int nt = 0; nt < 16; nt++) {
        float d0 = acc[nt][0] - mu0, d1 = acc[nt][1] - mu0;
        float d2 = acc[nt][2] - mu1, d3 = acc[nt][3] - mu1;
        var0 += d0 * d0 + d1 * d1;
        var1 += d2 * d2 + d3 * d3;
    }
    var0 += __shfl_xor_sync(0xffffffffu, var0, 1);
    var0 += __shfl_xor_sync(0xffffffffu, var0, 2);
    var1 += __shfl_xor_sync(0xffffffffu, var1, 1);
    var1 += __shfl_xor_sync(0xffffffffu, var1, 2);
    const float rs0 = rsqrtf(var0 * (1.f / 128.f) + 1e-5f);
    const float rs1 = rsqrtf(var1 * (1.f / 128.f) + 1e-5f);

    const float m0 = mask[b * NTOK + qrow] ? 0.f : 1.f;
    const float m1 = mask[b * NTOK + qrow + 8] ? 0.f : 1.f;

    float contrib[16][2];
#pragma unroll
    for (int nt = 0; nt < 16; nt++) {
        const int c = 8 * nt + cbase;
        const float g0 = bb[128 + c], g1 = bb[128 + c + 1];
        const float be0 = bb[256 + c], be1 = bb[256 + c + 1];
        float r00 = fmaxf((acc[nt][0] - mu0) * rs0 * g0 + be0, 0.f);
        float r01 = fmaxf((acc[nt][1] - mu0) * rs0 * g1 + be1, 0.f);
        float r10 = fmaxf((acc[nt][2] - mu1) * rs1 * g0 + be0, 0.f);
        float r11 = fmaxf((acc[nt][3] - mu1) * rs1 * g1 + be1, 0.f);
        contrib[nt][0] = r00 * m0 + r10 * m1;
        contrib[nt][1] = r01 * m0 + r11 * m1;
    }
#pragma unroll
    for (int nt = 0; nt < 16; nt++) {
#pragma unroll
        for (int off = 4; off < 32; off <<= 1) {
            contrib[nt][0] += __shfl_xor_sync(0xffffffffu, contrib[nt][0], off);
            contrib[nt][1] += __shfl_xor_sync(0xffffffffu, contrib[nt][1], off);
        }
    }
    float* poolw = (float*)(sm + FA_POOL);
    if ((lid >> 2) == 0) {
#pragma unroll
        for (int nt = 0; nt < 16; nt++)
            *(float2*)&poolw[wid * 128 + 8 * nt + cbase] =
                make_float2(contrib[nt][0], contrib[nt][1]);
    }
    __syncthreads();
    if (tid < 128) {
        float s = 0.f;
#pragma unroll
        for (int w = 0; w < 8; w++) s += poolw[w * 128 + tid];
        pp[((long)b * 16 + blockIdx.x) * 128 + tid] = s;
    }
}

// ---------------- prep: weight transposes + bias concat + input convert ----------------
__device__ __forceinline__ void tr_tile(const float* __restrict__ X, __half* __restrict__ Tt,
                                        int R, int Cc, int txi, int tyi, float scale)
{
    __shared__ float t[32][33];
    const int c0 = txi * 32, r0 = tyi * 32;
    for (int i = threadIdx.y; i < 32; i += 8)
        t[i][threadIdx.x] = X[(long)(r0 + i) * Cc + c0 + threadIdx.x];
    __syncthreads();
    for (int i = threadIdx.y; i < 32; i += 8) {
        long o = (long)(c0 + i) * R + r0 + threadIdx.x;
        Tt[o] = __float2half(t[threadIdx.x][i] * scale);
    }
}

// q weights/bias pre-scaled by 1/sqrt(D) = 1/16 so attention scores come out scaled.
__global__ void prep_kernel(
    const float* __restrict__ enc_w, const float* __restrict__ wq,
    const float* __restrict__ wk, const float* __restrict__ wv,
    const float* __restrict__ bn_w,
    const float* __restrict__ bq, const float* __restrict__ bk,
    const float* __restrict__ bv, const float* __restrict__ local_feat,
    __half* __restrict__ ent, __half* __restrict__ wqkvt, __half* __restrict__ bnt,
    float* __restrict__ bqkv, __half* __restrict__ lf)
{
    const int t = blockIdx.x;
    if (t < 128)        tr_tile(enc_w, ent, CLIPD, DD, t & 7, t >> 3, 1.f);
    else if (t < 192) { int i = t - 128; tr_tile(wq, wqkvt,            DD, DD, i & 7, i >> 3, 0.0625f); }
    else if (t < 256) { int i = t - 192; tr_tile(wk, wqkvt + 256 * DD, DD, DD, i & 7, i >> 3, 1.f); }
    else if (t < 320) { int i = t - 256; tr_tile(wv, wqkvt + 512 * DD, DD, DD, i & 7, i >> 3, 1.f); }
    else if (t < 352) { int i = t - 320; tr_tile(bn_w, bnt, DD, BDIM, i & 3, i >> 2, 1.f); }
    else if (t == 352) {
        const int id = threadIdx.y * 32 + threadIdx.x;
        bqkv[id]       = bq[id] * 0.0625f;
        bqkv[256 + id] = bk[id];
        bqkv[512 + id] = bv[id];
    } else {
        const int i = (t - 353) * 256 + threadIdx.y * 32 + threadIdx.x;
        const int n4 = ROWS * CLIPD / 4;
        if (i < n4) {
            float4 v = ((const float4*)local_feat)[i];
            __half2 a; a.x = __float2half(v.x); a.y = __float2half(v.y);
            __half2 b; b.x = __float2half(v.z); b.y = __float2half(v.w);
            ((__half2*)lf)[i * 2 + 0] = a;
            ((__half2*)lf)[i * 2 + 1] = b;
        }
    }
}

// ---------------- warp-per-row LayerNorm + ReLU (D=256) ----------------
__global__ void __launch_bounds__(256) ln_relu_kernel(
    const float* __restrict__ X, const float* __restrict__ g,
    const float* __restrict__ beta, __half* __restrict__ h16)
{
    const int wid = threadIdx.x >> 5, lid = threadIdx.x & 31;
    const long row = (long)blockIdx.x * 8 + wid;
    const float4* xr = (const float4*)(X + row * DD);
    float4 v0 = xr[lid], v1 = xr[lid + 32];

    float s = v0.x + v0.y + v0.z + v0.w + v1.x + v1.y + v1.z + v1.w;
#pragma unroll
    for (int o = 16; o; o >>= 1) s += __shfl_xor_sync(0xffffffffu, s, o);
    const float mu = s * (1.f / 256.f);

    float d0x = v0.x - mu, d0y = v0.y - mu, d0z = v0.z - mu, d0w = v0.w - mu;
    float d1x = v1.x - mu, d1y = v1.y - mu, d1z = v1.z - mu, d1w = v1.w - mu;
    float vs = d0x * d0x + d0y * d0y + d0z * d0z + d0w * d0w
             + d1x * d1x + d1y * d1y + d1z * d1z + d1w * d1w;
#pragma unroll
    for (int o = 16; o; o >>= 1) vs += __shfl_xor_sync(0xffffffffu, vs, o);
    const float rstd = rsqrtf(vs * (1.f / 256.f) + 1e-5f);

    float4 g0 = ((const float4*)g)[lid],    g1 = ((const float4*)g)[lid + 32];
    float4 b0 = ((const float4*)beta)[lid], b1 = ((const float4*)beta)[lid + 32];

    __half2 h0, h1, h2, h3;
    h0.x = __float2half(fmaxf(d0x * rstd * g0.x + b0.x, 0.f));
    h0.y = __float2half(fmaxf(d0y * rstd * g0.y + b0.y, 0.f));
    h1.x = __float2half(fmaxf(d0z * rstd * g0.z + b0.z, 0.f));
    h1.y = __float2half(fmaxf(d0w * rstd * g0.w + b0.w, 0.f));
    h2.x = __float2half(fmaxf(d1x * rstd * g1.x + b1.x, 0.f));
    h2.y = __float2half(fmaxf(d1y * rstd * g1.y + b1.y, 0.f));
    h3.x = __float2half(fmaxf(d1z * rstd * g1.z + b1.z, 0.f));
    h3.y = __float2half(fmaxf(d1w * rstd * g1.w + b1.w, 0.f));
    __half2* yr = (__half2*)(h16 + row * DD);
    yr[lid * 2 + 0] = h0; yr[lid * 2 + 1] = h1;
    yr[64 + lid * 2 + 0] = h2; yr[64 + lid * 2 + 1] = h3;
}

// ---------------- block reduction (head) ----------------
__device__ __forceinline__ float blk_sum(float v) {
    __shared__ float sh[33];
    int lane = threadIdx.x & 31, w = threadIdx.x >> 5;
#pragma unroll
    for (int o = 16; o; o >>= 1) v += __shfl_xor_sync(0xffffffffu, v, o);
    __syncthreads();
    if (lane == 0) sh[w] = v;
    __syncthreads();
    if (threadIdx.x == 0) {
        float s = 0.f; int nw = (blockDim.x + 31) >> 5;
        for (int i = 0; i < nw; i++) s += sh[i];
        sh[32] = s;
    }
    __syncthreads();
    return sh[32];
}

// ---------------- final: pooled + head MLP ----------------
__global__ void head_kernel(const float* __restrict__ pp, const int* __restrict__ mask,
                            const float* __restrict__ c1w, const float* __restrict__ c1b,
                            const float* __restrict__ c2w, const float* __restrict__ c2b,
                            float* __restrict__ out_f)
{
    const int b = blockIdx.x;
    const int t = threadIdx.x;  // 128
    __shared__ float sp[BDIM];
    __shared__ float hid[64];

    float cf = 0.f;
    for (int n = t; n < NTOK; n += 128) cf += mask[b * NTOK + n] ? 0.f : 1.f;
    const float cnt = fmaxf(blk_sum(cf), 1e-9f);

    float s = 0.f;
#pragma unroll
    for (int ch = 0; ch < 16; ch++) s += pp[((long)b * 16 + ch) * 128 + t];
    const float pooled = s / cnt;
    out_f[BB * NCLS + b * BDIM + t] = pooled;
    sp[t] = pooled;
    __syncthreads();

    if (t < 64) {
        float h = c1b[t];
        for (int i = 0; i < BDIM; i++) h += sp[i] * c1w[i * 64 + t];
        hid[t] = fmaxf(h, 0.f);
    }
    __syncthreads();
    if (t < NCLS) {
        float l = c2b[t];
        for (int j = 0; j < 64; j++) l += hid[j] * c2w[j * NCLS + t];
        out_f[b * NCLS + t] = l;
    }
}

// ---------------- launch ----------------
extern "C" void kernel_launch(void* const* d_in, const int* in_sizes, int n_in,
                              void* d_out, int out_size)
{
    const float* local_feat = (const float*)d_in[0];
    const float* coords     = (const float*)d_in[1];
    const int*   mask       = (const int*)d_in[2];
    const float* enc_w      = (const float*)d_in[3];
    const float* enc_b      = (const float*)d_in[4];
    const float* enc_g      = (const float*)d_in[5];
    const float* enc_beta   = (const float*)d_in[6];
    const float* gamma      = (const float*)d_in[7];
    const float* wq         = (const float*)d_in[8];
    const float* bq         = (const float*)d_in[9];
    const float* wk         = (const float*)d_in[10];
    const float* bk         = (const float*)d_in[11];
    const float* wv         = (const float*)d_in[12];
    const float* bv         = (const float*)d_in[13];
    const float* bn_w       = (const float*)d_in[14];
    const float* bn_b       = (const float*)d_in[15];
    const float* bn_g       = (const float*)d_in[16];
    const float* bn_beta    = (const float*)d_in[17];
    const float* c1_w       = (const float*)d_in[18];
    const float* c1_b       = (const float*)d_in[19];
    const float* c2_w       = (const float*)d_in[20];
    const float* c2_b       = (const float*)d_in[21];

    float *hf, *pp, *bqkv;
    __half *lf, *h16, *qkv, *ent, *wqkvt, *bnt;
    cudaGetSymbolAddress((void**)&lf,    g_lf);
    cudaGetSymbolAddress((void**)&hf,    g_hf);
    cudaGetSymbolAddress((void**)&h16,   g_h16);
    cudaGetSymbolAddress((void**)&qkv,   g_qkv);
    cudaGetSymbolAddress((void**)&ent,   g_ent);
    cudaGetSymbolAddress((void**)&wqkvt, g_wqkvt);
    cudaGetSymbolAddress((void**)&bqkv,  g_bqkv);
    cudaGetSymbolAddress((void**)&bnt,   g_bnt);
    cudaGetSymbolAddress((void**)&pp,    g_pp);

    cudaFuncSetAttribute(gemm_mma<false>, cudaFuncAttributeMaxDynamicSharedMemorySize, GEMM_SMEM);
    cudaFuncSetAttribute(gemm_mma<true>,  cudaFuncAttributeMaxDynamicSharedMemorySize, GEMM_SMEM);
    cudaFuncSetAttribute(flash_mega,      cudaFuncAttributeMaxDynamicSharedMemorySize, FA_SMEM);

    // 0) prep: transposes (+q prescale) + bias concat + input fp16 convert
    const int convBlocks = (ROWS * CLIPD / 4 + 255) / 256;
    prep_kernel<<<353 + convBlocks, dim3(32, 8)>>>(
        enc_w, wq, wk, wv, bn_w, bq, bk, bv, local_feat,
        ent, wqkvt, bnt, bqkv, lf);

    // 1) enc GEMM + LN
    gemm_mma<false><<<dim3(DD / 128, ROWS / 128), 256, GEMM_SMEM>>>(
        lf, ent, hf, nullptr, DD, CLIPD, 1.f, enc_b);
    ln_relu_kernel<<<ROWS / 8, 256>>>(hf, enc_g, enc_beta, h16);

    // 2) fused qkv GEMM  (M=16384, N=768, K=256)
    gemm_mma<true><<<dim3(QKVN / 128, ROWS / 128), 256, GEMM_SMEM>>>(
        h16, wqkvt, nullptr, qkv, QKVN, DD, 1.f, bqkv);

    // 3) mega fused attention + bn + LN + pool partials
    flash_mega<<<dim3(NTOK / 128, BB), 256, FA_SMEM>>>(
        qkv, coords, mask, gamma, bnt, bn_b, bn_g, bn_beta, pp);

    // 4) pooled + head -> d_out
    head_kernel<<<BB, 128>>>(pp, mask, c1_w, c1_b, c2_w, c2_b, (float*)d_out);
}

// round 16
// speedup vs baseline: 1.7295x; 1.0016x over previous
#include <cuda_runtime.h>
#include <cuda_fp16.h>
#include <math.h>
#include <stdint.h>

#define BB 8
#define NTOK 2048
#define CLIPD 512
#define DD 256
#define BDIM 128
#define NCLS 10
#define ROWS (BB * NTOK)   // 16384
#define QKVN 768

// ---------------- scratch (no cudaMalloc allowed) ----------------
__device__ __half g_lf  [ROWS * CLIPD];
__device__ float  g_hf  [ROWS * DD];
__device__ __half g_h16 [ROWS * DD];
__device__ __half g_qkv [ROWS * QKVN];         // q | k | v fp16, row stride 768 (q pre-scaled by 1/16)
__device__ __half g_ent [DD * CLIPD];
__device__ __half g_wqkvt[QKVN * DD];
__device__ float  g_bqkv[QKVN];
__device__ __half g_bnt [BDIM * DD];           // bn_w^T [128][256]
__device__ float  g_pp  [BB * 16 * BDIM];      // pool partials per (b, q-tile)

// ---------------- mma / ldmatrix / cp.async helpers ----------------
__device__ __forceinline__ uint32_t smem_u32(const void* p) {
    uint32_t a;
    asm("{ .reg .u64 t; cvta.to.shared.u64 t, %1; cvt.u32.u64 %0, t; }" : "=r"(a) : "l"(p));
    return a;
}
__device__ __forceinline__ void ldsm4(uint32_t* r, uint32_t addr) {
    asm volatile("ldmatrix.sync.aligned.m8n8.x4.shared.b16 {%0,%1,%2,%3}, [%4];"
                 : "=r"(r[0]), "=r"(r[1]), "=r"(r[2]), "=r"(r[3]) : "r"(addr));
}
__device__ __forceinline__ void ldsm4t(uint32_t* r, uint32_t addr) {
    asm volatile("ldmatrix.sync.aligned.m8n8.x4.trans.shared.b16 {%0,%1,%2,%3}, [%4];"
                 : "=r"(r[0]), "=r"(r[1]), "=r"(r[2]), "=r"(r[3]) : "r"(addr));
}
__device__ __forceinline__ void mma_f16(float* d, const uint32_t* a, const uint32_t* b) {
    asm volatile(
        "mma.sync.aligned.m16n8k16.row.col.f32.f16.f16.f32 "
        "{%0,%1,%2,%3}, {%4,%5,%6,%7}, {%8,%9}, {%0,%1,%2,%3};"
        : "+f"(d[0]), "+f"(d[1]), "+f"(d[2]), "+f"(d[3])
        : "r"(a[0]), "r"(a[1]), "r"(a[2]), "r"(a[3]), "r"(b[0]), "r"(b[1]));
}
__device__ __forceinline__ void cp16(uint32_t dst, const void* src) {
    asm volatile("cp.async.cg.shared.global [%0], [%1], 16;" :: "r"(dst), "l"(src));
}
#define CP_COMMIT() asm volatile("cp.async.commit_group;" ::: "memory")
#define CP_WAIT1()  asm volatile("cp.async.wait_group 1;" ::: "memory")
#define CP_WAIT0()  asm volatile("cp.async.wait_group 0;" ::: "memory")

// ---------------- fp16 HMMA GEMM, 3-stage cp.async pipeline ----------------
#define LDSR 40
#define STAGE_B (128 * LDSR * 2)
#define GEMM_SMEM (6 * STAGE_B)

template <bool HALF_OUT>
__global__ void __launch_bounds__(256) gemm_mma(
    const __half* __restrict__ A, const __half* __restrict__ B,
    float* __restrict__ C, __half* __restrict__ Ch,
    int N, int K, float alpha, const float* __restrict__ bias)
{
    extern __shared__ char smem[];
    const int tid = threadIdx.x;
    const int wid = tid >> 5, lid = tid & 31;
    const int wm = wid & 3, wn = wid >> 2;
    const int row0 = blockIdx.y * 128;
    const int col0 = blockIdx.x * 128;
    const int T = K / 32;

    const int lr = tid >> 1;
    const int lk = (tid & 1) * 16;

    const uint32_t sBase = smem_u32(smem);
    const uint32_t aS = sBase;
    const uint32_t bS = sBase + 3 * STAGE_B;
    const uint32_t dstOff = (uint32_t)(lr * LDSR + lk) * 2;

    const __half* ag = A + (long)(row0 + lr) * K + lk;
    const __half* bg = B + (long)(col0 + lr) * K + lk;

    auto issue = [&](int it, int buf) {
        const __half* ap = ag + it * 32;
        const __half* bp = bg + it * 32;
        const uint32_t ad = aS + buf * STAGE_B + dstOff;
        const uint32_t bd = bS + buf * STAGE_B + dstOff;
        cp16(ad, ap); cp16(ad + 16, ap + 8);
        cp16(bd, bp); cp16(bd + 16, bp + 8);
    };

    float acc[2][8][4];
#pragma unroll
    for (int i = 0; i < 2; i++)
#pragma unroll
        for (int j = 0; j < 8; j++)
#pragma unroll
            for (int e = 0; e < 4; e++) acc[i][j][e] = 0.f;

    issue(0, 0); CP_COMMIT();
    issue(1, 1); CP_COMMIT();

    const int arow = wm * 32 + (lid & 15);
    const int akof = (lid >> 4) * 8;
    const int brow = wn * 64 + (lid & 7) + (lid >> 4) * 8;
    const int bkof = ((lid >> 3) & 1) * 8;

    int buf = 0;
    for (int it = 0; it < T; ++it) {
        CP_WAIT1();
        __syncthreads();
        if (it + 2 < T) issue(it + 2, (buf + 2 >= 3) ? buf - 1 : buf + 2);
        CP_COMMIT();

        const uint32_t aBase = aS + buf * STAGE_B;
        const uint32_t bBase = bS + buf * STAGE_B;
#pragma unroll
        for (int ks = 0; ks < 2; ks++) {
            uint32_t af[2][4], bfr[4][4];
#pragma unroll
            for (int mt = 0; mt < 2; mt++)
                ldsm4(af[mt], aBase + (uint32_t)(((arow + mt * 16) * LDSR + ks * 16 + akof) * 2));
#pragma unroll
            for (int p = 0; p < 4; p++)
                ldsm4(bfr[p], bBase + (uint32_t)(((brow + p * 16) * LDSR + ks * 16 + bkof) * 2));
#pragma unroll
            for (int mt = 0; mt < 2; mt++)
#pragma unroll
                for (int nt = 0; nt < 8; nt++)
                    mma_f16(acc[mt][nt], af[mt], &bfr[nt >> 1][(nt & 1) * 2]);
        }
        buf = (buf + 1 >= 3) ? 0 : buf + 1;
    }

    const int mrow = row0 + wm * 32;
    const int ncol = col0 + wn * 64;
    const int r4 = lid >> 2, c2 = (lid & 3) * 2;
#pragma unroll
    for (int mt = 0; mt < 2; mt++) {
#pragma unroll
        for (int half = 0; half < 2; half++) {
            const long r = mrow + mt * 16 + r4 + half * 8;
#pragma unroll
            for (int nt = 0; nt < 8; nt++) {
                const int c = ncol + nt * 8 + c2;
                float v0 = alpha * acc[mt][nt][half * 2 + 0] + (bias ? bias[c + 0] : 0.f);
                float v1 = alpha * acc[mt][nt][half * 2 + 1] + (bias ? bias[c + 1] : 0.f);
                if (HALF_OUT) {
                    __half2 hh; hh.x = __float2half(v0); hh.y = __float2half(v1);
                    *(__half2*)&Ch[r * N + c] = hh;
                } else {
                    float2 o; o.x = v0; o.y = v1;
                    *(float2*)&C[r * N + c] = o;
                }
            }
        }
    }
}

// ---------------- mega fused flash: q-tile 128, kv-tile 64 ----------------
// q is pre-scaled by 1/sqrt(D) at the weight level, so S needs no scaling here.
#define QSTR 528
#define KVTILE 33792     // 64 * 528
#define FA_QS   0
#define FA_KS0  67584
#define FA_KS1  (FA_KS0 + KVTILE)
#define FA_VS0  (FA_KS1 + KVTILE)
#define FA_VS1  (FA_VS0 + KVTILE)
#define FA_META (FA_VS1 + KVTILE)      // 202752
#define FA_BIAS (FA_META + 2048)       // 204800
#define FA_POOL (FA_BIAS + 1536)       // 206336
#define FA_SMEM (FA_POOL + 4096)       // 210432

__global__ void __launch_bounds__(256) flash_mega(
    const __half* __restrict__ qkv, const float* __restrict__ coords,
    const int* __restrict__ mask,   const float* __restrict__ gamma,
    const __half* __restrict__ bnt, const float* __restrict__ bn_b,
    const float* __restrict__ bn_g, const float* __restrict__ bn_beta,
    float* __restrict__ pp)
{
    extern __shared__ char sm[];
    const int b = blockIdx.y;
    const int q0 = blockIdx.x * 128;
    const int tid = threadIdx.x, wid = tid >> 5, lid = tid & 31;

    const uint32_t S = smem_u32(sm);
    const uint32_t Qs = S + FA_QS;
    const uint32_t KsB[2] = {S + FA_KS0, S + FA_KS1};
    const uint32_t VsB[2] = {S + FA_VS0, S + FA_VS1};
    float4* meta = (float4*)(sm + FA_META);

    {
        const int row = tid >> 1, h = tid & 1;
        const __half* src = qkv + (long)(b * NTOK + q0 + row) * QKVN + h * 128;
        const uint32_t dst = Qs + row * QSTR + h * 256;
#pragma unroll
        for (int i = 0; i < 16; i++) cp16(dst + i * 16, src + i * 8);
    }
    auto issueKV = [&](int t, int bufi) {
        const int kv0 = t * 64;
        const int row = tid >> 2, q4 = tid & 3;
        const __half* base = qkv + (long)(b * NTOK + kv0 + row) * QKVN;
        {
            const __half* src = base + 256 + q4 * 64;
            const uint32_t dst = KsB[bufi] + row * QSTR + q4 * 128;
#pragma unroll
            for (int i = 0; i < 8; i++) cp16(dst + i * 16, src + i * 8);
        }
        {
            const __half* src = base + 512 + q4 * 64;
            const uint32_t dst = VsB[bufi] + row * QSTR + q4 * 128;
#pragma unroll
            for (int i = 0; i < 8; i++) cp16(dst + i * 16, src + i * 8);
        }
    };
    auto metaStore = [&](int t, int bufi) {
        if (tid < 64) {
            const int idx = b * NTOK + t * 64 + tid;
            float2 xy = ((const float2*)coords)[idx];
            int mk = mask[idx];
            meta[bufi * 64 + tid] = make_float4(xy.x, xy.y, xy.x * xy.x + xy.y * xy.y,
                                                mk ? 0.f : 1.f);
        }
    };
    issueKV(0, 0); CP_COMMIT();
    issueKV(1, 1); CP_COMMIT();
    metaStore(0, 0);
    metaStore(1, 1);

    const int qrow = q0 + wid * 16 + (lid >> 2);
    const float ga = fabsf(gamma[0]);
    float2 c0v = ((const float2*)coords)[b * NTOK + qrow];
    float2 c1v = ((const float2*)coords)[b * NTOK + qrow + 8];
    const float xn0 = c0v.x, yn0 = c0v.y, sqn0 = c0v.x * c0v.x + c0v.y * c0v.y;
    const float xn1 = c1v.x, yn1 = c1v.y, sqn1 = c1v.x * c1v.x + c1v.y * c1v.y;

    float M0 = -INFINITY, M1 = -INFINITY, Z0 = 0.f, Z1 = 0.f;
    float o[32][4];
#pragma unroll
    for (int i = 0; i < 32; i++)
#pragma unroll
        for (int e = 0; e < 4; e++) o[i][e] = 0.f;

    const int arow = wid * 16 + (lid & 15);
    const int akof = (lid >> 4) * 8;
    const int nrw = (lid & 7) + (lid >> 4) * 8;
    const int nkof = ((lid >> 3) & 1) * 8;
    const int vrow = lid & 15;
    const int vcb  = (lid >> 4) * 16;

    for (int t = 0; t < 32; ++t) {
        const int cur = t & 1;
        CP_WAIT1();
        __syncthreads();

        float s[8][4];
#pragma unroll
        for (int j = 0; j < 8; j++)
#pragma unroll
            for (int e = 0; e < 4; e++) s[j][e] = 0.f;
        const uint32_t kb = KsB[cur];
#pragma unroll
        for (int ks = 0; ks < 16; ks++) {
            uint32_t af[4], bfr[4][4];
            ldsm4(af, Qs + (uint32_t)(arow * QSTR + (ks * 16 + akof) * 2));
#pragma unroll
            for (int p = 0; p < 4; p++)
                ldsm4(bfr[p], kb + (uint32_t)((p * 16 + nrw) * QSTR + (ks * 16 + nkof) * 2));
#pragma unroll
            for (int nt = 0; nt < 8; nt++)
                mma_f16(s[nt], af, &bfr[nt >> 1][(nt & 1) * 2]);
        }

        // ---- online softmax (S already pre-scaled by 1/16 via q weights) ----
        float mx0 = -INFINITY, mx1 = -INFINITY;
#pragma unroll
        for (int j = 0; j < 8; j++) {
            mx0 = fmaxf(mx0, fmaxf(s[j][0], s[j][1]));
            mx1 = fmaxf(mx1, fmaxf(s[j][2], s[j][3]));
        }
        mx0 = fmaxf(mx0, __shfl_xor_sync(0xffffffffu, mx0, 1));
        mx0 = fmaxf(mx0, __shfl_xor_sync(0xffffffffu, mx0, 2));
        mx1 = fmaxf(mx1, __shfl_xor_sync(0xffffffffu, mx1, 1));
        mx1 = fmaxf(mx1, __shfl_xor_sync(0xffffffffu, mx1, 2));
        const float Mn0 = fmaxf(M0, mx0), Mn1 = fmaxf(M1, mx1);
        const float sc0 = __expf(M0 - Mn0), sc1 = __expf(M1 - Mn1);
        M0 = Mn0; M1 = Mn1;
        Z0 *= sc0; Z1 *= sc1;
        if (sc0 != 1.f || sc1 != 1.f) {
#pragma unroll
            for (int nt = 0; nt < 32; nt++) {
                o[nt][0] *= sc0; o[nt][1] *= sc0; o[nt][2] *= sc1; o[nt][3] *= sc1;
            }
        }

        uint32_t pf[16];
        const float4* mt = meta + cur * 64;
#pragma unroll
        for (int j = 0; j < 8; j++) {
            const int cc = 8 * j + (lid & 3) * 2;
            float4 ma = mt[cc], mb = mt[cc + 1];
            float e00 = __expf(s[j][0] - Mn0), e01 = __expf(s[j][1] - Mn0);
            float e10 = __expf(s[j][2] - Mn1), e11 = __expf(s[j][3] - Mn1);
            Z0 += e00 + e01; Z1 += e10 + e11;
            float d2a0 = fmaxf(sqn0 + ma.z - 2.f * (xn0 * ma.x + yn0 * ma.y), 0.f);
            float d2b0 = fmaxf(sqn0 + mb.z - 2.f * (xn0 * mb.x + yn0 * mb.y), 0.f);
            float d2a1 = fmaxf(sqn1 + ma.z - 2.f * (xn1 * ma.x + yn1 * ma.y), 0.f);
            float d2b1 = fmaxf(sqn1 + mb.z - 2.f * (xn1 * mb.x + yn1 * mb.y), 0.f);
            // dist = sqrt(d2) via single MUFU.RSQ: d2 * rsqrt(d2); exact 0 for d2 = 0.
            float da0 = d2a0 * rsqrtf(fmaxf(d2a0, 1e-20f));
            float db0 = d2b0 * rsqrtf(fmaxf(d2b0, 1e-20f));
            float da1 = d2a1 * rsqrtf(fmaxf(d2a1, 1e-20f));
            float db1 = d2b1 * rsqrtf(fmaxf(d2b1, 1e-20f));
            float n00 = e00 * __expf(-ga * da0) * ma.w;
            float n01 = e01 * __expf(-ga * db0) * mb.w;
            float n10 = e10 * __expf(-ga * da1) * ma.w;
            float n11 = e11 * __expf(-ga * db1) * mb.w;
            __half2 p0; p0.x = __float2half(n00); p0.y = __float2half(n01);
            __half2 p1; p1.x = __float2half(n10); p1.y = __float2half(n11);
            pf[2 * j + 0] = *(uint32_t*)&p0;
            pf[2 * j + 1] = *(uint32_t*)&p1;
        }

        const uint32_t vb = VsB[cur];
#pragma unroll
        for (int ks = 0; ks < 4; ks++) {
            uint32_t a[4] = {pf[4 * ks + 0], pf[4 * ks + 1], pf[4 * ks + 2], pf[4 * ks + 3]};
            const uint32_t rowb = vb + (uint32_t)((ks * 16 + vrow) * QSTR + vcb);
#pragma unroll
            for (int p = 0; p < 16; p++) {
                uint32_t bf4[4];
                ldsm4t(bf4, rowb + (uint32_t)(p * 32));
                mma_f16(o[2 * p + 0], a, &bf4[0]);
                mma_f16(o[2 * p + 1], a, &bf4[2]);
            }
        }

        __syncthreads();
        if (t + 2 < 32) {
            issueKV(t + 2, cur); CP_COMMIT();
            metaStore(t + 2, cur);
        } else {
            CP_COMMIT();
        }
    }

    Z0 += __shfl_xor_sync(0xffffffffu, Z0, 1);
    Z0 += __shfl_xor_sync(0xffffffffu, Z0, 2);
    Z1 += __shfl_xor_sync(0xffffffffu, Z1, 1);
    Z1 += __shfl_xor_sync(0xffffffffu, Z1, 2);
    const float i0 = 1.f / Z0, i1 = 1.f / Z1;

    CP_WAIT0();
    __syncthreads();
    {
        const int row = tid >> 1, h = tid & 1;
        const __half* src = bnt + (long)row * DD + h * 128;
        const uint32_t dst = Qs + row * QSTR + h * 256;
#pragma unroll
        for (int i = 0; i < 16; i++) cp16(dst + i * 16, src + i * 8);
        CP_COMMIT();
        float* bb = (float*)(sm + FA_BIAS);
        if (tid < 128)      bb[tid] = bn_b[tid];
        else                bb[tid] = bn_g[tid - 128];
        if (tid < 128)      bb[256 + tid] = bn_beta[tid];
    }
    CP_WAIT0();
    __syncthreads();

    float acc[16][4];
#pragma unroll
    for (int nt = 0; nt < 16; nt++)
#pragma unroll
        for (int e = 0; e < 4; e++) acc[nt][e] = 0.f;

#pragma unroll
    for (int ks = 0; ks < 16; ks++) {
        __half2 t0 = __floats2half2_rn(o[2 * ks][0] * i0, o[2 * ks][1] * i0);
        __half2 t1 = __floats2half2_rn(o[2 * ks][2] * i1, o[2 * ks][3] * i1);
        __half2 t2 = __floats2half2_rn(o[2 * ks + 1][0] * i0, o[2 * ks + 1][1] * i0);
        __half2 t3 = __floats2half2_rn(o[2 * ks + 1][2] * i1, o[2 * ks + 1][3] * i1);
        uint32_t a[4] = {*(uint32_t*)&t0, *(uint32_t*)&t1, *(uint32_t*)&t2, *(uint32_t*)&t3};
#pragma unroll
        for (int p = 0; p < 8; p++) {
            uint32_t bf4[4];
            ldsm4(bf4, Qs + (uint32_t)((p * 16 + nrw) * QSTR + (ks * 16 + nkof) * 2));
            mma_f16(acc[2 * p + 0], a, &bf4[0]);
            mma_f16(acc[2 * p + 1], a, &bf4[2]);
        }
    }

    const float* bb = (const float*)(sm + FA_BIAS);
    const int cbase = (lid & 3) * 2;
    float mu0 = 0.f, mu1 = 0.f;
#pragma unroll
    for (int nt = 0; nt < 16; nt++) {
        const int c = 8 * nt + cbase;
        acc[nt][0] += bb[c]; acc[nt][1] += bb[c + 1];
        acc[nt][2] += bb[c]; acc[nt][3] += bb[c + 1];
        mu0 += acc[nt][0] + acc[nt][1];
        mu1 += acc[nt][2] + acc[nt][3];
    }
    mu0 += __shfl_xor_sync(0xffffffffu, mu0, 1);
    mu0 += __shfl_xor_sync(0xffffffffu, mu0, 2);
    mu1 += __shfl_xor_sync(0xffffffffu, mu1, 1);
    mu1 += __shfl_xor_sync(0xffffffffu, mu1, 2);
    mu0 *= (1.f / 128.f); mu1 *= (1.f / 128.f);

    float var0 = 0.f, var1 = 0.f;
#pragma unroll
    for (int nt = 0; nt < 16; nt++) {
        float d0 = acc[nt][0] - mu0, d1 = acc[nt][1] - mu0;
        float d2 = acc[nt][2] - mu1, d3 = acc[nt][3] - mu1;
        var0 += d0 * d0 + d1 * d1;
        var1 += d2 * d2 + d3 * d3;
    }
    var0 += __shfl_xor_sync(0xffffffffu, var0, 1);
    var0 += __shfl_xor_sync(0xffffffffu, var0, 2);
    var1 += __shfl_xor_sync(0xffffffffu, var1, 1);
    var1 += __shfl_xor_sync(0xffffffffu, var1, 2);
    const float rs0 = rsqrtf(var0 * (1.f / 128.f) + 1e-5f);
    const float rs1 = rsqrtf(var1 * (1.f / 128.f) + 1e-5f);

    const float m0 = mask[b * NTOK + qrow] ? 0.f : 1.f;
    const float m1 = mask[b * NTOK + qrow + 8] ? 0.f : 1.f;

    float contrib[16][2];
#pragma unroll
    for (int nt = 0; nt < 16; nt++) {
        const int c = 8 * nt + cbase;
        const float g0 = bb[128 + c], g1 = bb[128 + c + 1];
        const float be0 = bb[256 + c], be1 = bb[256 + c + 1];
        float r00 = fmaxf((acc[nt][0] - mu0) * rs0 * g0 + be0, 0.f);
        float r01 = fmaxf((acc[nt][1] - mu0) * rs0 * g1 + be1, 0.f);
        float r10 = fmaxf((acc[nt][2] - mu1) * rs1 * g0 + be0, 0.f);
        float r11 = fmaxf((acc[nt][3] - mu1) * rs1 * g1 + be1, 0.f);
        contrib[nt][0] = r00 * m0 + r10 * m1;
        contrib[nt][1] = r01 * m0 + r11 * m1;
    }
#pragma unroll
    for (int nt = 0; nt < 16; nt++) {
#pragma unroll
        for (int off = 4; off < 32; off <<= 1) {
            contrib[nt][0] += __shfl_xor_sync(0xffffffffu, contrib[nt][0], off);
            contrib[nt][1] += __shfl_xor_sync(0xffffffffu, contrib[nt][1], off);
        }
    }
    float* poolw = (float*)(sm + FA_POOL);
    if ((lid >> 2) == 0) {
#pragma unroll
        for (int nt = 0; nt < 16; nt++)
            *(float2*)&poolw[wid * 128 + 8 * nt + cbase] =
                make_float2(contrib[nt][0], contrib[nt][1]);
    }
    __syncthreads();
    if (tid < 128) {
        float s = 0.f;
#pragma unroll
        for (int w = 0; w < 8; w++) s += poolw[w * 128 + tid];
        pp[((long)b * 16 + blockIdx.x) * 128 + tid] = s;
    }
}

// ---------------- prep: weight transposes + bias concat + input convert ----------------
__device__ __forceinline__ void tr_tile(const float* __restrict__ X, __half* __restrict__ Tt,
                                        int R, int Cc, int txi, int tyi, float scale)
{
    __shared__ float t[32][33];
    const int c0 = txi * 32, r0 = tyi * 32;
    for (int i = threadIdx.y; i < 32; i += 8)
        t[i][threadIdx.x] = X[(long)(r0 + i) * Cc + c0 + threadIdx.x];
    __syncthreads();
    for (int i = threadIdx.y; i < 32; i += 8) {
        long o = (long)(c0 + i) * R + r0 + threadIdx.x;
        Tt[o] = __float2half(t[threadIdx.x][i] * scale);
    }
}

// q weights/bias pre-scaled by 1/sqrt(D) = 1/16 so attention scores come out scaled.
__global__ void prep_kernel(
    const float* __restrict__ enc_w, const float* __restrict__ wq,
    const float* __restrict__ wk, const float* __restrict__ wv,
    const float* __restrict__ bn_w,
    const float* __restrict__ bq, const float* __restrict__ bk,
    const float* __restrict__ bv, const float* __restrict__ local_feat,
    __half* __restrict__ ent, __half* __restrict__ wqkvt, __half* __restrict__ bnt,
    float* __restrict__ bqkv, __half* __restrict__ lf)
{
    const int t = blockIdx.x;
    if (t < 128)        tr_tile(enc_w, ent, CLIPD, DD, t & 7, t >> 3, 1.f);
    else if (t < 192) { int i = t - 128; tr_tile(wq, wqkvt,            DD, DD, i & 7, i >> 3, 0.0625f); }
    else if (t < 256) { int i = t - 192; tr_tile(wk, wqkvt + 256 * DD, DD, DD, i & 7, i >> 3, 1.f); }
    else if (t < 320) { int i = t - 256; tr_tile(wv, wqkvt + 512 * DD, DD, DD, i & 7, i >> 3, 1.f); }
    else if (t < 352) { int i = t - 320; tr_tile(bn_w, bnt, DD, BDIM, i & 3, i >> 2, 1.f); }
    else if (t == 352) {
        const int id = threadIdx.y * 32 + threadIdx.x;
        bqkv[id]       = bq[id] * 0.0625f;
        bqkv[256 + id] = bk[id];
        bqkv[512 + id] = bv[id];
    } else {
        const int i = (t - 353) * 256 + threadIdx.y * 32 + threadIdx.x;
        const int n4 = ROWS * CLIPD / 4;
        if (i < n4) {
            float4 v = ((const float4*)local_feat)[i];
            __half2 a; a.x = __float2half(v.x); a.y = __float2half(v.y);
            __half2 b; b.x = __float2half(v.z); b.y = __float2half(v.w);
            ((__half2*)lf)[i * 2 + 0] = a;
            ((__half2*)lf)[i * 2 + 1] = b;
        }
    }
}

// ---------------- warp-per-row LayerNorm + ReLU (D=256) ----------------
__global__ void __launch_bounds__(256) ln_relu_kernel(
    const float* __restrict__ X, const float* __restrict__ g,
    const float* __restrict__ beta, __half* __restrict__ h16)
{
    const int wid = threadIdx.x >> 5, lid = threadIdx.x & 31;
    const long row = (long)blockIdx.x * 8 + wid;
    const float4* xr = (const float4*)(X + row * DD);
    float4 v0 = xr[lid], v1 = xr[lid + 32];

    float s = v0.x + v0.y + v0.z + v0.w + v1.x + v1.y + v1.z + v1.w;
#pragma unroll
    for (int o = 16; o; o >>= 1) s += __shfl_xor_sync(0xffffffffu, s, o);
    const float mu = s * (1.f / 256.f);

    float d0x = v0.x - mu, d0y = v0.y - mu, d0z = v0.z - mu, d0w = v0.w - mu;
    float d1x = v1.x - mu, d1y = v1.y - mu, d1z = v1.z - mu, d1w = v1.w - mu;
    float vs = d0x * d0x + d0y * d0y + d0z * d0z + d0w * d0w
             + d1x * d1x + d1y * d1y + d1z * d1z + d1w * d1w;
#pragma unroll
    for (int o = 16; o; o >>= 1) vs += __shfl_xor_sync(0xffffffffu, vs, o);
    const float rstd = rsqrtf(vs * (1.f / 256.f) + 1e-5f);

    float4 g0 = ((const float4*)g)[lid],    g1 = ((const float4*)g)[lid + 32];
    float4 b0 = ((const float4*)beta)[lid], b1 = ((const float4*)beta)[lid + 32];

    __half2 h0, h1, h2, h3;
    h0.x = __float2half(fmaxf(d0x * rstd * g0.x + b0.x, 0.f));
    h0.y = __float2half(fmaxf(d0y * rstd * g0.y + b0.y, 0.f));
    h1.x = __float2half(fmaxf(d0z * rstd * g0.z + b0.z, 0.f));
    h1.y = __float2half(fmaxf(d0w * rstd * g0.w + b0.w, 0.f));
    h2.x = __float2half(fmaxf(d1x * rstd * g1.x + b1.x, 0.f));
    h2.y = __float2half(fmaxf(d1y * rstd * g1.y + b1.y, 0.f));
    h3.x = __float2half(fmaxf(d1z * rstd * g1.z + b1.z, 0.f));
    h3.y = __float2half(fmaxf(d1w * rstd * g1.w + b1.w, 0.f));
    __half2* yr = (__half2*)(h16 + row * DD);
    yr[lid * 2 + 0] = h0; yr[lid * 2 + 1] = h1;
    yr[64 + lid * 2 + 0] = h2; yr[64 + lid * 2 + 1] = h3;
}

// ---------------- block reduction (head) ----------------
__device__ __forceinline__ float blk_sum(float v) {
    __shared__ float sh[33];
    int lane = threadIdx.x & 31, w = threadIdx.x >> 5;
#pragma unroll
    for (int o = 16; o; o >>= 1) v += __shfl_xor_sync(0xffffffffu, v, o);
    __syncthreads();
    if (lane == 0) sh[w] = v;
    __syncthreads();
    if (threadIdx.x == 0) {
        float s = 0.f; int nw = (blockDim.x + 31) >> 5;
        for (int i = 0; i < nw; i++) s += sh[i];
        sh[32] = s;
    }
    __syncthreads();
    return sh[32];
}

// ---------------- final: pooled + head MLP ----------------
__global__ void head_kernel(const float* __restrict__ pp, const int* __restrict__ mask,
                            const float* __restrict__ c1w, const float* __restrict__ c1b,
                            const float* __restrict__ c2w, const float* __restrict__ c2b,
                            float* __restrict__ out_f)
{
    const int b = blockIdx.x;
    const int t = threadIdx.x;  // 128
    __shared__ float sp[BDIM];
    __shared__ float hid[64];

    float cf = 0.f;
    for (int n = t; n < NTOK; n += 128) cf += mask[b * NTOK + n] ? 0.f : 1.f;
    const float cnt = fmaxf(blk_sum(cf), 1e-9f);

    float s = 0.f;
#pragma unroll
    for (int ch = 0; ch < 16; ch++) s += pp[((long)b * 16 + ch) * 128 + t];
    const float pooled = s / cnt;
    out_f[BB * NCLS + b * BDIM + t] = pooled;
    sp[t] = pooled;
    __syncthreads();

    if (t < 64) {
        float h = c1b[t];
        for (int i = 0; i < BDIM; i++) h += sp[i] * c1w[i * 64 + t];
        hid[t] = fmaxf(h, 0.f);
    }
    __syncthreads();
    if (t < NCLS) {
        float l = c2b[t];
        for (int j = 0; j < 64; j++) l += hid[j] * c2w[j * NCLS + t];
        out_f[b * NCLS + t] = l;
    }
}

// ---------------- launch ----------------
extern "C" void kernel_launch(void* const* d_in, const int* in_sizes, int n_in,
                              void* d_out, int out_size)
{
    const float* local_feat = (const float*)d_in[0];
    const float* coords     = (const float*)d_in[1];
    const int*   mask       = (const int*)d_in[2];
    const float* enc_w      = (const float*)d_in[3];
    const float* enc_b      = (const float*)d_in[4];
    const float* enc_g      = (const float*)d_in[5];
    const float* enc_beta   = (const float*)d_in[6];
    const float* gamma      = (const float*)d_in[7];
    const float* wq         = (const float*)d_in[8];
    const float* bq         = (const float*)d_in[9];
    const float* wk         = (const float*)d_in[10];
    const float* bk         = (const float*)d_in[11];
    const float* wv         = (const float*)d_in[12];
    const float* bv         = (const float*)d_in[13];
    const float* bn_w       = (const float*)d_in[14];
    const float* bn_b       = (const float*)d_in[15];
    const float* bn_g       = (const float*)d_in[16];
    const float* bn_beta    = (const float*)d_in[17];
    const float* c1_w       = (const float*)d_in[18];
    const float* c1_b       = (const float*)d_in[19];
    const float* c2_w       = (const float*)d_in[20];
    const float* c2_b       = (const float*)d_in[21];

    float *hf, *pp, *bqkv;
    __half *lf, *h16, *qkv, *ent, *wqkvt, *bnt;
    cudaGetSymbolAddress((void**)&lf,    g_lf);
    cudaGetSymbolAddress((void**)&hf,    g_hf);
    cudaGetSymbolAddress((void**)&h16,   g_h16);
    cudaGetSymbolAddress((void**)&qkv,   g_qkv);
    cudaGetSymbolAddress((void**)&ent,   g_ent);
    cudaGetSymbolAddress((void**)&wqkvt, g_wqkvt);
    cudaGetSymbolAddress((void**)&bqkv,  g_bqkv);
    cudaGetSymbolAddress((void**)&bnt,   g_bnt);
    cudaGetSymbolAddress((void**)&pp,    g_pp);

    cudaFuncSetAttribute(gemm_mma<false>, cudaFuncAttributeMaxDynamicSharedMemorySize, GEMM_SMEM);
    cudaFuncSetAttribute(gemm_mma<true>,  cudaFuncAttributeMaxDynamicSharedMemorySize, GEMM_SMEM);
    cudaFuncSetAttribute(flash_mega,      cudaFuncAttributeMaxDynamicSharedMemorySize, FA_SMEM);

    // 0) prep: transposes (+q prescale) + bias concat + input fp16 convert
    const int convBlocks = (ROWS * CLIPD / 4 + 255) / 256;
    prep_kernel<<<353 + convBlocks, dim3(32, 8)>>>(
        enc_w, wq, wk, wv, bn_w, bq, bk, bv, local_feat,
        ent, wqkvt, bnt, bqkv, lf);

    // 1) enc GEMM + LN
    gemm_mma<false><<<dim3(DD / 128, ROWS / 128), 256, GEMM_SMEM>>>(
        lf, ent, hf, nullptr, DD, CLIPD, 1.f, enc_b);
    ln_relu_kernel<<<ROWS / 8, 256>>>(hf, enc_g, enc_beta, h16);

    // 2) fused qkv GEMM  (M=16384, N=768, K=256)
    gemm_mma<true><<<dim3(QKVN / 128, ROWS / 128), 256, GEMM_SMEM>>>(
        h16, wqkvt, nullptr, qkv, QKVN, DD, 1.f, bqkv);

    // 3) mega fused attention + bn + LN + pool partials
    flash_mega<<<dim3(NTOK / 128, BB), 256, FA_SMEM>>>(
        qkv, coords, mask, gamma, bnt, bn_b, bn_g, bn_beta, pp);

    // 4) pooled + head -> d_out
    head_kernel<<<BB, 128>>>(pp, mask, c1_w, c1_b, c2_w, c2_b, (float*)d_out);
}